// round 10
// baseline (speedup 1.0000x reference)
#include <cuda_runtime.h>
#include <cuda_bf16.h>
#include <math.h>
#include <stdint.h>

// ---------------------------------------------------------------------------
// Problem constants
// ---------------------------------------------------------------------------
#define N_NODES 50000
#define N_EDGES 10000
#define NNZ     400000
#define QDIM    128
#define VDIM    256
#define EDIM    256
#define KIN     256
#define NEG_SLOPE 0.01f
#define SCORE_SCALE 0.08838834764831845f   // 1/sqrt(128)

#define F1W 512   // k1 | v1 | q2
#define F2W 384   // k2 | v2

// ---------------------------------------------------------------------------
// Static scratch
// ---------------------------------------------------------------------------
__device__ float g_fused1[N_NODES * F1W];
__device__ float g_fused2[N_EDGES * F2W];
__device__ float g_q1[N_EDGES * QDIM];
__device__ float g_Wcomb[F1W * KIN];
__device__ float g_bcomb[F1W];
__device__ float g_Wcat2[F2W * EDIM];
__device__ float g_bcat2[F2W];
__device__ int   g_counts[N_NODES];
__device__ int   g_offsets[N_NODES + 1];
__device__ int   g_cursor[N_NODES];
__device__ int   g_perm[NNZ];
__device__ int   g_partials[64];

// ---------------------------------------------------------------------------
// Weight pre-combination (eliminates feat_v GEMM): Wcomb = Wcat1 @ Wvtx
// ---------------------------------------------------------------------------
__global__ __launch_bounds__(256) void combine_w_kernel(
    const float* __restrict__ Wkv, const float* __restrict__ Wvv,
    const float* __restrict__ Wqv, const float* __restrict__ Wvtx,
    float* __restrict__ Wcomb)
{
    __shared__ float a[8][256];
    const int ob = blockIdx.x * 8;
    const int i = threadIdx.x;
#pragma unroll
    for (int r = 0; r < 8; r++) {
        const int o = ob + r;
        const float* src = (o < 128) ? Wkv + (size_t)o * 256
                         : (o < 384) ? Wvv + (size_t)(o - 128) * 256
                                     : Wqv + (size_t)(o - 384) * 256;
        a[r][i] = src[i];
    }
    __syncthreads();
    float s[8];
#pragma unroll
    for (int r = 0; r < 8; r++) s[r] = 0.f;
    for (int v = 0; v < 256; v++) {
        const float w = Wvtx[(size_t)v * 256 + i];
#pragma unroll
        for (int r = 0; r < 8; r++) s[r] += a[r][v] * w;
    }
#pragma unroll
    for (int r = 0; r < 8; r++) Wcomb[(size_t)(ob + r) * 256 + i] = s[r];
}

__global__ void combine_b_kernel(
    const float* __restrict__ Wkv, const float* __restrict__ Wvv,
    const float* __restrict__ Wqv,
    const float* __restrict__ bkv, const float* __restrict__ bvv,
    const float* __restrict__ bqv, const float* __restrict__ bvtx,
    float* __restrict__ bcomb)
{
    const int o = blockIdx.x * blockDim.x + threadIdx.x;
    if (o >= F1W) return;
    const float* wsrc;
    float b;
    if (o < 128)      { wsrc = Wkv + (size_t)o * 256;         b = bkv[o]; }
    else if (o < 384) { wsrc = Wvv + (size_t)(o - 128) * 256; b = bvv[o - 128]; }
    else              { wsrc = Wqv + (size_t)(o - 384) * 256; b = bqv[o - 384]; }
    float s = b;
    for (int v = 0; v < 256; v++) s += wsrc[v] * bvtx[v];
    bcomb[o] = s;
}

// ---------------------------------------------------------------------------
// bf16-split tensor-core GEMM (best measured variant, unchanged)
// ---------------------------------------------------------------------------
#define BM 128
#define BN 64
#define BK 32
#define SS2 20

__device__ __forceinline__ void mma_bf16(float* c,
    uint32_t a0, uint32_t a1, uint32_t a2, uint32_t a3,
    uint32_t b0, uint32_t b1)
{
    asm volatile(
        "mma.sync.aligned.m16n8k16.row.col.f32.bf16.bf16.f32 "
        "{%0,%1,%2,%3}, {%4,%5,%6,%7}, {%8,%9}, {%0,%1,%2,%3};"
        : "+f"(c[0]), "+f"(c[1]), "+f"(c[2]), "+f"(c[3])
        : "r"(a0), "r"(a1), "r"(a2), "r"(a3), "r"(b0), "r"(b1));
}

__device__ __forceinline__ uint2 split2(float x0, float x1)
{
    __nv_bfloat16 h0 = __float2bfloat16_rn(x0);
    __nv_bfloat16 h1 = __float2bfloat16_rn(x1);
    __nv_bfloat16 l0 = __float2bfloat16_rn(x0 - __bfloat162float(h0));
    __nv_bfloat16 l1 = __float2bfloat16_rn(x1 - __bfloat162float(h1));
    uint2 r;
    r.x = (uint32_t)__bfloat16_as_ushort(h0) | ((uint32_t)__bfloat16_as_ushort(h1) << 16);
    r.y = (uint32_t)__bfloat16_as_ushort(l0) | ((uint32_t)__bfloat16_as_ushort(l1) << 16);
    return r;
}

__global__ __launch_bounds__(256, 2) void gemm_bf16_kernel(
    const float* __restrict__ A, const float* __restrict__ W,
    const float* __restrict__ bias, float* __restrict__ C,
    int M, int N, int K)
{
    __shared__ uint2 As2[BM][SS2];
    __shared__ uint2 Bs2[BN][SS2];

    const int t    = threadIdx.x;
    const int lane = t & 31;
    const int wid  = t >> 5;
    const int wm   = wid & 3;
    const int wn   = wid >> 2;
    const int g    = lane >> 2;
    const int t4   = lane & 3;

    const int block_m = blockIdx.y * BM;
    const int block_n = blockIdx.x * BN;

    const int arow_i = t >> 1;
    const int aseg   = (t & 1) * 16;
    const int brow_i = t >> 2;
    const int bseg   = (t & 3) * 8;
    const int gma = block_m + arow_i;
    const float* aptr = A + (size_t)(gma < M ? gma : (M - 1)) * K + aseg;
    const float* bptr = W + (size_t)(block_n + brow_i) * K + bseg;

    float acc[2][4][4];
#pragma unroll
    for (int i = 0; i < 2; i++)
#pragma unroll
        for (int j = 0; j < 4; j++)
#pragma unroll
            for (int l = 0; l < 4; l++) acc[i][j][l] = 0.f;

    float4 pa[4], pb[2];
#pragma unroll
    for (int u = 0; u < 4; u++) pa[u] = *(const float4*)(aptr + u * 4);
#pragma unroll
    for (int u = 0; u < 2; u++) pb[u] = *(const float4*)(bptr + u * 4);

    const int NC = K / BK;
    for (int c = 0; c < NC; c++) {
#pragma unroll
        for (int u = 0; u < 4; u++) {
            uint2 p0 = split2(pa[u].x, pa[u].y);
            uint2 p1 = split2(pa[u].z, pa[u].w);
            asm volatile("st.shared.v4.b32 [%0], {%1,%2,%3,%4};" ::
                "l"(__cvta_generic_to_shared(&As2[arow_i][aseg / 2 + u * 2])),
                "r"(p0.x), "r"(p0.y), "r"(p1.x), "r"(p1.y) : "memory");
        }
#pragma unroll
        for (int u = 0; u < 2; u++) {
            uint2 p0 = split2(pb[u].x, pb[u].y);
            uint2 p1 = split2(pb[u].z, pb[u].w);
            asm volatile("st.shared.v4.b32 [%0], {%1,%2,%3,%4};" ::
                "l"(__cvta_generic_to_shared(&Bs2[brow_i][bseg / 2 + u * 2])),
                "r"(p0.x), "r"(p0.y), "r"(p1.x), "r"(p1.y) : "memory");
        }
        __syncthreads();

        if (c + 1 < NC) {
            const int k1o = (c + 1) * BK;
#pragma unroll
            for (int u = 0; u < 4; u++) pa[u] = *(const float4*)(aptr + k1o + u * 4);
#pragma unroll
            for (int u = 0; u < 2; u++) pb[u] = *(const float4*)(bptr + k1o + u * 4);
        }

#pragma unroll
        for (int kk = 0; kk < 2; kk++) {
            const int kc0 = kk * 8 + t4;
            const int kc1 = kc0 + 4;
            uint32_t ahi[2][4], alo[2][4];
#pragma unroll
            for (int mt = 0; mt < 2; mt++) {
                const int r0 = wm * 32 + mt * 16 + g;
                uint2 v0 = As2[r0][kc0];
                uint2 v1 = As2[r0 + 8][kc0];
                uint2 v2 = As2[r0][kc1];
                uint2 v3 = As2[r0 + 8][kc1];
                ahi[mt][0] = v0.x; alo[mt][0] = v0.y;
                ahi[mt][1] = v1.x; alo[mt][1] = v1.y;
                ahi[mt][2] = v2.x; alo[mt][2] = v2.y;
                ahi[mt][3] = v3.x; alo[mt][3] = v3.y;
            }
            uint32_t bhi[4][2], blo[4][2];
#pragma unroll
            for (int nt = 0; nt < 4; nt++) {
                const int n0 = wn * 32 + nt * 8 + g;
                uint2 u0 = Bs2[n0][kc0];
                uint2 u1 = Bs2[n0][kc1];
                bhi[nt][0] = u0.x; blo[nt][0] = u0.y;
                bhi[nt][1] = u1.x; blo[nt][1] = u1.y;
            }
#pragma unroll
            for (int mt = 0; mt < 2; mt++)
#pragma unroll
                for (int nt = 0; nt < 4; nt++)
                    mma_bf16(acc[mt][nt], ahi[mt][0], ahi[mt][1], ahi[mt][2], ahi[mt][3],
                             bhi[nt][0], bhi[nt][1]);
#pragma unroll
            for (int mt = 0; mt < 2; mt++)
#pragma unroll
                for (int nt = 0; nt < 4; nt++)
                    mma_bf16(acc[mt][nt], ahi[mt][0], ahi[mt][1], ahi[mt][2], ahi[mt][3],
                             blo[nt][0], blo[nt][1]);
#pragma unroll
            for (int mt = 0; mt < 2; mt++)
#pragma unroll
                for (int nt = 0; nt < 4; nt++)
                    mma_bf16(acc[mt][nt], alo[mt][0], alo[mt][1], alo[mt][2], alo[mt][3],
                             bhi[nt][0], bhi[nt][1]);
        }
        __syncthreads();
    }

#pragma unroll
    for (int mt = 0; mt < 2; mt++) {
#pragma unroll
        for (int nt = 0; nt < 4; nt++) {
            const int m0 = block_m + wm * 32 + mt * 16 + g;
            const int n0 = block_n + wn * 32 + nt * 8 + t4 * 2;
            const float bv0 = bias[n0], bv1 = bias[n0 + 1];
            if (m0 < M) {
                float2 o = make_float2(acc[mt][nt][0] + bv0, acc[mt][nt][1] + bv1);
                *(float2*)&C[(size_t)m0 * N + n0] = o;
            }
            if (m0 + 8 < M) {
                float2 o = make_float2(acc[mt][nt][2] + bv0, acc[mt][nt][3] + bv1);
                *(float2*)&C[(size_t)(m0 + 8) * N + n0] = o;
            }
        }
    }
}

static void run_gemm(const float* A, const float* W, const float* b, float* C,
                     int M, int N, int K)
{
    dim3 grid(N / BN, (M + BM - 1) / BM);
    gemm_bf16_kernel<<<grid, 256>>>(A, W, b, C, M, N, K);
}

// ---------------------------------------------------------------------------
// CSR machinery: histogram -> scan -> perm
// ---------------------------------------------------------------------------
__global__ void init_counts_kernel(int* counts, int n)
{
    int i = blockIdx.x * blockDim.x + threadIdx.x;
    if (i < n) counts[i] = 0;
}

__global__ void hist_kernel(const int* __restrict__ seg, int* __restrict__ counts, int nnz)
{
    int i = blockIdx.x * blockDim.x + threadIdx.x;
    if (i < nnz) atomicAdd(&counts[seg[i]], 1);
}

__global__ __launch_bounds__(1024) void scan_block_kernel(
    const int* __restrict__ counts, int* __restrict__ offsets,
    int* __restrict__ partials, int n)
{
    __shared__ int sh[1024];
    const int t = threadIdx.x;
    const int i = blockIdx.x * 1024 + t;
    const int x = (i < n) ? counts[i] : 0;
    sh[t] = x;
    __syncthreads();
    for (int off = 1; off < 1024; off <<= 1) {
        int v = (t >= off) ? sh[t - off] : 0;
        __syncthreads();
        sh[t] += v;
        __syncthreads();
    }
    if (i < n) offsets[i] = sh[t] - x;
    if (t == 1023) partials[blockIdx.x] = sh[1023];
}

__global__ void scan_partials_kernel(int* partials, int* offsets, int nb, int n)
{
    __shared__ int sh[64];
    const int t = threadIdx.x;
    const int x = (t < nb) ? partials[t] : 0;
    sh[t] = x;
    __syncthreads();
    for (int off = 1; off < 64; off <<= 1) {
        int v = (t >= off) ? sh[t - off] : 0;
        __syncthreads();
        sh[t] += v;
        __syncthreads();
    }
    if (t < nb) partials[t] = sh[t] - x;
    if (t == 63) offsets[n] = sh[63];
}

__global__ void scan_add_kernel(int* __restrict__ offsets, int* __restrict__ cursor,
                                const int* __restrict__ partials, int n)
{
    int i = blockIdx.x * blockDim.x + threadIdx.x;
    if (i < n) {
        int v = offsets[i] + partials[i >> 10];
        offsets[i] = v;
        cursor[i] = v;
    }
}

__global__ void build_perm_kernel(const int* __restrict__ seg, int* __restrict__ cursor,
                                  int* __restrict__ perm, int nnz)
{
    int i = blockIdx.x * blockDim.x + threadIdx.x;
    if (i < nnz) {
        int pos = atomicAdd(&cursor[seg[i]], 1);
        perm[pos] = i;
    }
}

// ---------------------------------------------------------------------------
// Fused attention pass: score + online softmax + aggregate, one block/segment.
// q row index == segment id. k and v live in the SAME matrix row (koff/voff).
// ---------------------------------------------------------------------------
__global__ __launch_bounds__(256) void fused_attn_kernel(
    const float* __restrict__ mat, int mstride, int voff,
    const float* __restrict__ qmat, int qstride,
    const int* __restrict__ rowidx,
    const int* __restrict__ offsets, const int* __restrict__ perm,
    float* __restrict__ out, int nseg)
{
    __shared__ int   sh_r[128];
    __shared__ float sh_s[128];
    __shared__ float red[8];

    const int s = blockIdx.x;
    if (s >= nseg) return;
    const int t = threadIdx.x;
    const int lane = t & 31;
    const int wid  = t >> 5;
    const int beg = offsets[s];
    const int end = offsets[s + 1];
    const int d = t;   // output dim 0..255

    // q fragment per lane (k-dot uses dims lane*4 .. lane*4+3)
    const float4 qf = *(const float4*)&qmat[(size_t)s * qstride + lane * 4];

    float m = -INFINITY, ssum = 0.f, acc = 0.f;

    for (int cb = beg; cb < end; cb += 128) {
        const int cnt = min(128, end - cb);
        if (t < cnt) sh_r[t] = rowidx[perm[cb + t]];
        __syncthreads();

        // ---- scores: warp `wid` handles entries wid, wid+8, ... ----
        for (int j = wid; j < cnt; j += 8) {
            const float4 kf = *(const float4*)&mat[(size_t)sh_r[j] * mstride + lane * 4];
            float dsum = kf.x * qf.x + kf.y * qf.y + kf.z * qf.z + kf.w * qf.w;
#pragma unroll
            for (int o = 16; o > 0; o >>= 1) dsum += __shfl_xor_sync(0xffffffffu, dsum, o);
            if (lane == 0)
                sh_s[j] = (dsum >= 0.f ? dsum : NEG_SLOPE * dsum) * SCORE_SCALE;
        }
        __syncthreads();

        // ---- chunk max ----
        float v = (t < cnt) ? sh_s[t] : -INFINITY;
        float wmax = v;
#pragma unroll
        for (int o = 16; o > 0; o >>= 1) wmax = fmaxf(wmax, __shfl_xor_sync(0xffffffffu, wmax, o));
        if (lane == 0) red[wid] = wmax;
        __syncthreads();
        const float cmax = fmaxf(fmaxf(fmaxf(red[0], red[1]), fmaxf(red[2], red[3])),
                                 fmaxf(fmaxf(red[4], red[5]), fmaxf(red[6], red[7])));
        const float newm = fmaxf(m, cmax);
        __syncthreads();   // everyone has cmax before red is reused

        // ---- exp weights + chunk sum ----
        float e = 0.f;
        if (t < cnt) { e = __expf(sh_s[t] - newm); sh_s[t] = e; }
        float wsum = e;
#pragma unroll
        for (int o = 16; o > 0; o >>= 1) wsum += __shfl_xor_sync(0xffffffffu, wsum, o);
        if (lane == 0) red[wid] = wsum;
        __syncthreads();
        const float csum = ((red[0] + red[1]) + (red[2] + red[3]))
                         + ((red[4] + red[5]) + (red[6] + red[7]));

        const float rescale = __expf(m - newm);   // 0 on first chunk (m=-inf): acc,ssum are 0
        acc = acc * rescale;
        ssum = ssum * rescale + csum;
        m = newm;

        // ---- aggregate v rows (4 independent chains) ----
        float p0 = 0.f, p1 = 0.f, p2 = 0.f, p3 = 0.f;
        int j = 0;
        for (; j + 4 <= cnt; j += 4) {
            p0 += sh_s[j]     * mat[(size_t)sh_r[j]     * mstride + voff + d];
            p1 += sh_s[j + 1] * mat[(size_t)sh_r[j + 1] * mstride + voff + d];
            p2 += sh_s[j + 2] * mat[(size_t)sh_r[j + 2] * mstride + voff + d];
            p3 += sh_s[j + 3] * mat[(size_t)sh_r[j + 3] * mstride + voff + d];
        }
        for (; j < cnt; j++)
            p0 += sh_s[j] * mat[(size_t)sh_r[j] * mstride + voff + d];
        acc += (p0 + p1) + (p2 + p3);
        __syncthreads();   // sh_r/sh_s reused next chunk
    }

    out[(size_t)s * 256 + d] = fmaxf(acc / fmaxf(ssum, 1e-20f), 0.f);
}

// ---------------------------------------------------------------------------
// Launch
// ---------------------------------------------------------------------------
extern "C" void kernel_launch(void* const* d_in, const int* in_sizes, int n_in,
                              void* d_out, int out_size)
{
    const float* vfeat    = (const float*)d_in[0];
    const float* efeat    = (const float*)d_in[1];
    const int*   node_idx = (const int*)d_in[2];
    const int*   edge_idx = (const int*)d_in[3];
    const float* W_vtx = (const float*)d_in[4];  const float* b_vtx = (const float*)d_in[5];
    const float* W_qe  = (const float*)d_in[6];  const float* b_qe  = (const float*)d_in[7];
    const float* W_kv  = (const float*)d_in[8];  const float* b_kv  = (const float*)d_in[9];
    const float* W_vv  = (const float*)d_in[10]; const float* b_vv  = (const float*)d_in[11];
    const float* W_qv  = (const float*)d_in[12]; const float* b_qv  = (const float*)d_in[13];
    const float* W_ke  = (const float*)d_in[14]; const float* b_ke  = (const float*)d_in[15];
    const float* W_ve  = (const float*)d_in[16]; const float* b_ve  = (const float*)d_in[17];

    float* out_v = (float*)d_out;
    float* out_e = out_v + (size_t)N_NODES * VDIM;

    float *fused1, *fused2, *q1, *Wcomb, *bcomb, *Wcat2, *bcat2;
    int *counts, *offsets, *cursor, *perm, *partials;
    cudaGetSymbolAddress((void**)&fused1, g_fused1);
    cudaGetSymbolAddress((void**)&fused2, g_fused2);
    cudaGetSymbolAddress((void**)&q1, g_q1);
    cudaGetSymbolAddress((void**)&Wcomb, g_Wcomb);
    cudaGetSymbolAddress((void**)&bcomb, g_bcomb);
    cudaGetSymbolAddress((void**)&Wcat2, g_Wcat2);
    cudaGetSymbolAddress((void**)&bcat2, g_bcat2);
    cudaGetSymbolAddress((void**)&counts, g_counts);
    cudaGetSymbolAddress((void**)&offsets, g_offsets);
    cudaGetSymbolAddress((void**)&cursor, g_cursor);
    cudaGetSymbolAddress((void**)&perm, g_perm);
    cudaGetSymbolAddress((void**)&partials, g_partials);

    const int nnzBlocks = (NNZ + 255) / 256;

    // ---- weight pre-combination + concat ----
    combine_w_kernel<<<F1W / 8, 256>>>(W_kv, W_vv, W_qv, W_vtx, Wcomb);
    combine_b_kernel<<<2, 256>>>(W_kv, W_vv, W_qv, b_kv, b_vv, b_qv, b_vtx, bcomb);
    cudaMemcpyAsync(Wcat2,             W_ke, (size_t)QDIM * EDIM * 4, cudaMemcpyDeviceToDevice);
    cudaMemcpyAsync(Wcat2 + 128 * 256, W_ve, (size_t)VDIM * EDIM * 4, cudaMemcpyDeviceToDevice);
    cudaMemcpyAsync(bcat2,       b_ke, QDIM * 4, cudaMemcpyDeviceToDevice);
    cudaMemcpyAsync(bcat2 + 128, b_ve, VDIM * 4, cudaMemcpyDeviceToDevice);

    // ---- projections ----
    run_gemm(vfeat, Wcomb, bcomb, fused1, N_NODES, F1W,  KIN);   // k1|v1|q2
    run_gemm(efeat, W_qe,  b_qe,  q1,     N_EDGES, QDIM, KIN);   // q1

    // ---- pass 1: nodes -> hyperedges (seg = edge_idx, nseg = N_EDGES) ----
    {
        const int nseg = N_EDGES;
        const int nb = (nseg + 1023) / 1024;
        init_counts_kernel<<<(nseg + 255) / 256, 256>>>(counts, nseg);
        hist_kernel<<<nnzBlocks, 256>>>(edge_idx, counts, NNZ);
        scan_block_kernel<<<nb, 1024>>>(counts, offsets, partials, nseg);
        scan_partials_kernel<<<1, 64>>>(partials, offsets, nb, nseg);
        scan_add_kernel<<<(nseg + 255) / 256, 256>>>(offsets, cursor, partials, nseg);
        build_perm_kernel<<<nnzBlocks, 256>>>(edge_idx, cursor, perm, NNZ);
        fused_attn_kernel<<<nseg, 256>>>(fused1, F1W, 128, q1, QDIM,
                                         node_idx, offsets, perm, out_e, nseg);
    }

    // ---- edge-side fused projection ----
    run_gemm(out_e, Wcat2, bcat2, fused2, N_EDGES, F2W, EDIM);   // k2|v2

    // ---- pass 2: hyperedges -> nodes (seg = node_idx, nseg = N_NODES) ----
    {
        const int nseg = N_NODES;
        const int nb = (nseg + 1023) / 1024;
        init_counts_kernel<<<(nseg + 255) / 256, 256>>>(counts, nseg);
        hist_kernel<<<nnzBlocks, 256>>>(node_idx, counts, NNZ);
        scan_block_kernel<<<nb, 1024>>>(counts, offsets, partials, nseg);
        scan_partials_kernel<<<1, 64>>>(partials, offsets, nb, nseg);
        scan_add_kernel<<<(nseg + 255) / 256, 256>>>(offsets, cursor, partials, nseg);
        build_perm_kernel<<<nnzBlocks, 256>>>(node_idx, cursor, perm, NNZ);
        fused_attn_kernel<<<nseg, 256>>>(fused2, F2W, 128, fused1 + 384, F1W,
                                         edge_idx, offsets, perm, out_v, nseg);
    }
}

// round 11
// speedup vs baseline: 1.0511x; 1.0511x over previous
#include <cuda_runtime.h>
#include <cuda_bf16.h>
#include <math.h>
#include <stdint.h>

// ---------------------------------------------------------------------------
// Problem constants
// ---------------------------------------------------------------------------
#define N_NODES 50000
#define N_EDGES 10000
#define NNZ     400000
#define QDIM    128
#define VDIM    256
#define EDIM    256
#define KIN     256
#define NEG_SLOPE 0.01f
#define SCORE_SCALE 0.08838834764831845f   // 1/sqrt(128)

#define F1W 512   // k1 | v1 | q2
#define F2W 384   // k2 | v2

// ---------------------------------------------------------------------------
// Static scratch
// ---------------------------------------------------------------------------
__device__ float g_fused1[N_NODES * F1W];
__device__ float g_fused2[N_EDGES * F2W];
__device__ float g_q1[N_EDGES * QDIM];
__device__ float g_Wcomb[F1W * KIN];
__device__ float g_bcomb[F1W];
__device__ float g_Wcat2[F2W * EDIM];
__device__ float g_bcat2[F2W];
__device__ int   g_cnt_e[N_EDGES];
__device__ int   g_cnt_n[N_NODES];
__device__ int   g_off_e[N_EDGES + 1];
__device__ int   g_off_n[N_NODES + 1];
__device__ int   g_cur_e[N_EDGES];
__device__ int   g_cur_n[N_NODES];
__device__ float g_segsum_e[N_EDGES];
__device__ float g_segsum_n[N_NODES];
__device__ int   g_rows[NNZ];
__device__ float g_ew[NNZ];
__device__ int   g_partials[80];

// ---------------------------------------------------------------------------
// Weight pre-combination (eliminates feat_v GEMM): Wcomb = Wcat1 @ Wvtx
// ---------------------------------------------------------------------------
__global__ __launch_bounds__(256) void combine_w_kernel(
    const float* __restrict__ Wkv, const float* __restrict__ Wvv,
    const float* __restrict__ Wqv, const float* __restrict__ Wvtx,
    float* __restrict__ Wcomb)
{
    __shared__ float a[8][256];
    const int ob = blockIdx.x * 8;
    const int i = threadIdx.x;
#pragma unroll
    for (int r = 0; r < 8; r++) {
        const int o = ob + r;
        const float* src = (o < 128) ? Wkv + (size_t)o * 256
                         : (o < 384) ? Wvv + (size_t)(o - 128) * 256
                                     : Wqv + (size_t)(o - 384) * 256;
        a[r][i] = src[i];
    }
    __syncthreads();
    float s[8];
#pragma unroll
    for (int r = 0; r < 8; r++) s[r] = 0.f;
    for (int v = 0; v < 256; v++) {
        const float w = Wvtx[(size_t)v * 256 + i];
#pragma unroll
        for (int r = 0; r < 8; r++) s[r] += a[r][v] * w;
    }
#pragma unroll
    for (int r = 0; r < 8; r++) Wcomb[(size_t)(ob + r) * 256 + i] = s[r];
}

__global__ void combine_b_kernel(
    const float* __restrict__ Wkv, const float* __restrict__ Wvv,
    const float* __restrict__ Wqv,
    const float* __restrict__ bkv, const float* __restrict__ bvv,
    const float* __restrict__ bqv, const float* __restrict__ bvtx,
    float* __restrict__ bcomb)
{
    const int o = blockIdx.x * blockDim.x + threadIdx.x;
    if (o >= F1W) return;
    const float* wsrc;
    float b;
    if (o < 128)      { wsrc = Wkv + (size_t)o * 256;         b = bkv[o]; }
    else if (o < 384) { wsrc = Wvv + (size_t)(o - 128) * 256; b = bvv[o - 128]; }
    else              { wsrc = Wqv + (size_t)(o - 384) * 256; b = bqv[o - 384]; }
    float s = b;
    for (int v = 0; v < 256; v++) s += wsrc[v] * bvtx[v];
    bcomb[o] = s;
}

// ---------------------------------------------------------------------------
// bf16-split tensor-core GEMM body (proven R5/R9 inner loop)
// ---------------------------------------------------------------------------
#define BM 128
#define BN 64
#define BK 32
#define SS2 20

__device__ __forceinline__ void mma_bf16(float* c,
    uint32_t a0, uint32_t a1, uint32_t a2, uint32_t a3,
    uint32_t b0, uint32_t b1)
{
    asm volatile(
        "mma.sync.aligned.m16n8k16.row.col.f32.bf16.bf16.f32 "
        "{%0,%1,%2,%3}, {%4,%5,%6,%7}, {%8,%9}, {%0,%1,%2,%3};"
        : "+f"(c[0]), "+f"(c[1]), "+f"(c[2]), "+f"(c[3])
        : "r"(a0), "r"(a1), "r"(a2), "r"(a3), "r"(b0), "r"(b1));
}

__device__ __forceinline__ uint2 split2(float x0, float x1)
{
    __nv_bfloat16 h0 = __float2bfloat16_rn(x0);
    __nv_bfloat16 h1 = __float2bfloat16_rn(x1);
    __nv_bfloat16 l0 = __float2bfloat16_rn(x0 - __bfloat162float(h0));
    __nv_bfloat16 l1 = __float2bfloat16_rn(x1 - __bfloat162float(h1));
    uint2 r;
    r.x = (uint32_t)__bfloat16_as_ushort(h0) | ((uint32_t)__bfloat16_as_ushort(h1) << 16);
    r.y = (uint32_t)__bfloat16_as_ushort(l0) | ((uint32_t)__bfloat16_as_ushort(l1) << 16);
    return r;
}

__device__ __forceinline__ void gemm_body(
    const float* __restrict__ A, const float* __restrict__ W,
    const float* __restrict__ bias, float* __restrict__ C,
    int M, int N, int K, int bxx, int byy)
{
    __shared__ uint2 As2[BM][SS2];
    __shared__ uint2 Bs2[BN][SS2];

    const int t    = threadIdx.x;
    const int lane = t & 31;
    const int wid  = t >> 5;
    const int wm   = wid & 3;
    const int wn   = wid >> 2;
    const int g    = lane >> 2;
    const int t4   = lane & 3;

    const int block_m = byy * BM;
    const int block_n = bxx * BN;

    const int arow_i = t >> 1;
    const int aseg   = (t & 1) * 16;
    const int brow_i = t >> 2;
    const int bseg   = (t & 3) * 8;
    const int gma = block_m + arow_i;
    const float* aptr = A + (size_t)(gma < M ? gma : (M - 1)) * K + aseg;
    const float* bptr = W + (size_t)(block_n + brow_i) * K + bseg;

    float acc[2][4][4];
#pragma unroll
    for (int i = 0; i < 2; i++)
#pragma unroll
        for (int j = 0; j < 4; j++)
#pragma unroll
            for (int l = 0; l < 4; l++) acc[i][j][l] = 0.f;

    float4 pa[4], pb[2];
#pragma unroll
    for (int u = 0; u < 4; u++) pa[u] = *(const float4*)(aptr + u * 4);
#pragma unroll
    for (int u = 0; u < 2; u++) pb[u] = *(const float4*)(bptr + u * 4);

    const int NC = K / BK;
    for (int c = 0; c < NC; c++) {
#pragma unroll
        for (int u = 0; u < 4; u++) {
            uint2 p0 = split2(pa[u].x, pa[u].y);
            uint2 p1 = split2(pa[u].z, pa[u].w);
            asm volatile("st.shared.v4.b32 [%0], {%1,%2,%3,%4};" ::
                "l"(__cvta_generic_to_shared(&As2[arow_i][aseg / 2 + u * 2])),
                "r"(p0.x), "r"(p0.y), "r"(p1.x), "r"(p1.y) : "memory");
        }
#pragma unroll
        for (int u = 0; u < 2; u++) {
            uint2 p0 = split2(pb[u].x, pb[u].y);
            uint2 p1 = split2(pb[u].z, pb[u].w);
            asm volatile("st.shared.v4.b32 [%0], {%1,%2,%3,%4};" ::
                "l"(__cvta_generic_to_shared(&Bs2[brow_i][bseg / 2 + u * 2])),
                "r"(p0.x), "r"(p0.y), "r"(p1.x), "r"(p1.y) : "memory");
        }
        __syncthreads();

        if (c + 1 < NC) {
            const int k1o = (c + 1) * BK;
#pragma unroll
            for (int u = 0; u < 4; u++) pa[u] = *(const float4*)(aptr + k1o + u * 4);
#pragma unroll
            for (int u = 0; u < 2; u++) pb[u] = *(const float4*)(bptr + k1o + u * 4);
        }

#pragma unroll
        for (int kk = 0; kk < 2; kk++) {
            const int kc0 = kk * 8 + t4;
            const int kc1 = kc0 + 4;
            uint32_t ahi[2][4], alo[2][4];
#pragma unroll
            for (int mt = 0; mt < 2; mt++) {
                const int r0 = wm * 32 + mt * 16 + g;
                uint2 v0 = As2[r0][kc0];
                uint2 v1 = As2[r0 + 8][kc0];
                uint2 v2 = As2[r0][kc1];
                uint2 v3 = As2[r0 + 8][kc1];
                ahi[mt][0] = v0.x; alo[mt][0] = v0.y;
                ahi[mt][1] = v1.x; alo[mt][1] = v1.y;
                ahi[mt][2] = v2.x; alo[mt][2] = v2.y;
                ahi[mt][3] = v3.x; alo[mt][3] = v3.y;
            }
            uint32_t bhi[4][2], blo[4][2];
#pragma unroll
            for (int nt = 0; nt < 4; nt++) {
                const int n0 = wn * 32 + nt * 8 + g;
                uint2 u0 = Bs2[n0][kc0];
                uint2 u1 = Bs2[n0][kc1];
                bhi[nt][0] = u0.x; blo[nt][0] = u0.y;
                bhi[nt][1] = u1.x; blo[nt][1] = u1.y;
            }
#pragma unroll
            for (int mt = 0; mt < 2; mt++)
#pragma unroll
                for (int nt = 0; nt < 4; nt++)
                    mma_bf16(acc[mt][nt], ahi[mt][0], ahi[mt][1], ahi[mt][2], ahi[mt][3],
                             bhi[nt][0], bhi[nt][1]);
#pragma unroll
            for (int mt = 0; mt < 2; mt++)
#pragma unroll
                for (int nt = 0; nt < 4; nt++)
                    mma_bf16(acc[mt][nt], ahi[mt][0], ahi[mt][1], ahi[mt][2], ahi[mt][3],
                             blo[nt][0], blo[nt][1]);
#pragma unroll
            for (int mt = 0; mt < 2; mt++)
#pragma unroll
                for (int nt = 0; nt < 4; nt++)
                    mma_bf16(acc[mt][nt], alo[mt][0], alo[mt][1], alo[mt][2], alo[mt][3],
                             bhi[nt][0], bhi[nt][1]);
        }
        __syncthreads();
    }

#pragma unroll
    for (int mt = 0; mt < 2; mt++) {
#pragma unroll
        for (int nt = 0; nt < 4; nt++) {
            const int m0 = block_m + wm * 32 + mt * 16 + g;
            const int n0 = block_n + wn * 32 + nt * 8 + t4 * 2;
            const float bv0 = bias[n0], bv1 = bias[n0 + 1];
            if (m0 < M) {
                float2 o = make_float2(acc[mt][nt][0] + bv0, acc[mt][nt][1] + bv1);
                *(float2*)&C[(size_t)m0 * N + n0] = o;
            }
            if (m0 + 8 < M) {
                float2 o = make_float2(acc[mt][nt][2] + bv0, acc[mt][nt][3] + bv1);
                *(float2*)&C[(size_t)(m0 + 8) * N + n0] = o;
            }
        }
    }
}

// single GEMM
__global__ __launch_bounds__(256, 2) void gemm_bf16_kernel(
    const float* __restrict__ A, const float* __restrict__ W,
    const float* __restrict__ bias, float* __restrict__ C,
    int M, int N, int K)
{
    gemm_body(A, W, bias, C, M, N, K, blockIdx.x, blockIdx.y);
}

// dual GEMM: blocks [0,nb0) -> gemm0, rest -> gemm1 (fills gemm1 into gemm0's tail)
__global__ __launch_bounds__(256, 2) void gemm_dual_kernel(
    const float* __restrict__ A0, const float* __restrict__ W0,
    const float* __restrict__ b0, float* __restrict__ C0, int M0, int N0,
    const float* __restrict__ A1, const float* __restrict__ W1,
    const float* __restrict__ b1, float* __restrict__ C1, int M1, int N1,
    int K, int nb0)
{
    int b = blockIdx.x;
    if (b < nb0) {
        const int gx = N0 / BN;
        gemm_body(A0, W0, b0, C0, M0, N0, K, b % gx, b / gx);
    } else {
        b -= nb0;
        const int gx = N1 / BN;
        gemm_body(A1, W1, b1, C1, M1, N1, K, b % gx, b / gx);
    }
}

// ---------------------------------------------------------------------------
// Upfront CSR build for BOTH passes (dual kernels)
// ---------------------------------------------------------------------------
__global__ void init_dual_kernel(int* cnt_e, int* cnt_n, float* ss_e, float* ss_n)
{
    int i = blockIdx.x * blockDim.x + threadIdx.x;
    if (i < N_EDGES) { cnt_e[i] = 0; ss_e[i] = 0.f; }
    if (i < N_NODES) { cnt_n[i] = 0; ss_n[i] = 0.f; }
}

__global__ void hist_dual_kernel(const int* __restrict__ eidx, const int* __restrict__ nidx,
                                 int* __restrict__ cnt_e, int* __restrict__ cnt_n, int nnz)
{
    int i = blockIdx.x * blockDim.x + threadIdx.x;
    if (i < nnz) {
        atomicAdd(&cnt_e[eidx[i]], 1);
        atomicAdd(&cnt_n[nidx[i]], 1);
    }
}

__device__ __forceinline__ void scan_block_body(
    const int* counts, int* offsets, int* partials, int n, int blk)
{
    __shared__ int sh[1024];
    const int t = threadIdx.x;
    const int i = blk * 1024 + t;
    const int x = (i < n) ? counts[i] : 0;
    sh[t] = x;
    __syncthreads();
    for (int off = 1; off < 1024; off <<= 1) {
        int v = (t >= off) ? sh[t - off] : 0;
        __syncthreads();
        sh[t] += v;
        __syncthreads();
    }
    if (i < n) offsets[i] = sh[t] - x;
    if (t == 1023) partials[blk] = sh[1023];
}

#define NB_E ((N_EDGES + 1023) / 1024)   // 10
#define NB_N ((N_NODES + 1023) / 1024)   // 49

__global__ __launch_bounds__(1024) void scan_dual_block_kernel(
    const int* cnt_e, int* off_e, const int* cnt_n, int* off_n, int* partials)
{
    const int b = blockIdx.x;
    if (b < NB_E) scan_block_body(cnt_e, off_e, partials, N_EDGES, b);
    else          scan_block_body(cnt_n, off_n, partials + 16, N_NODES, b - NB_E);
}

__global__ void scan_serial_kernel(int* partials, int* off_e, int* off_n)
{
    if (threadIdx.x == 0) {
        int run = 0;
        for (int i = 0; i < NB_E; i++) { int t = partials[i]; partials[i] = run; run += t; }
        off_e[N_EDGES] = NNZ;
    } else if (threadIdx.x == 1) {
        int run = 0;
        for (int i = 0; i < NB_N; i++) { int t = partials[16 + i]; partials[16 + i] = run; run += t; }
        off_n[N_NODES] = NNZ;
    }
}

__global__ void scan_add_dual_kernel(int* off_e, int* cur_e, int* off_n, int* cur_n,
                                     const int* partials)
{
    int i = blockIdx.x * blockDim.x + threadIdx.x;
    if (i < N_EDGES) {
        int v = off_e[i] + partials[i >> 10];
        off_e[i] = v;
        cur_e[i] = v;
    }
    if (i < N_NODES) {
        int v = off_n[i] + partials[16 + (i >> 10)];
        off_n[i] = v;
        cur_n[i] = v;
    }
}

// ---------------------------------------------------------------------------
// Fused score+exp+scatter: warp per nnz. No segmax (scores are O(1); softmax
// is shift-invariant, reference's max-subtract is stability-only).
// Writes rows/ew in CSR-sorted position -> aggregate reads coalesced.
// ---------------------------------------------------------------------------
__global__ __launch_bounds__(256) void score_fused_kernel(
    const float* __restrict__ kmat, int kstride,
    const float* __restrict__ qmat, int qstride,
    const int* __restrict__ kidx, const int* __restrict__ seg,
    float* __restrict__ segsum, int* __restrict__ cursor,
    int* __restrict__ rows, float* __restrict__ ew, int nnz)
{
    const int w = (blockIdx.x * blockDim.x + threadIdx.x) >> 5;
    const int lane = threadIdx.x & 31;
    if (w >= nnz) return;
    const int ki = kidx[w];
    const int sg = seg[w];
    float4 a = *(const float4*)&kmat[(size_t)ki * kstride + lane * 4];
    float4 b = *(const float4*)&qmat[(size_t)sg * qstride + lane * 4];
    float d = a.x * b.x + a.y * b.y + a.z * b.z + a.w * b.w;
#pragma unroll
    for (int o = 16; o > 0; o >>= 1) d += __shfl_xor_sync(0xffffffffu, d, o);
    if (lane == 0) {
        const float s = (d >= 0.f ? d : NEG_SLOPE * d) * SCORE_SCALE;
        const float e = __expf(s);
        atomicAdd(&segsum[sg], e);
        const int pos = atomicAdd(&cursor[sg], 1);
        rows[pos] = ki;
        ew[pos] = e;
    }
}

// ---------------------------------------------------------------------------
// Aggregate: one block/segment, 256 threads = 256 dims; coalesced CSR reads.
// ---------------------------------------------------------------------------
__global__ __launch_bounds__(256) void aggregate_kernel(
    const float* __restrict__ vmat, int vstride, int voff,
    const int* __restrict__ rows, const float* __restrict__ ew,
    const int* __restrict__ offsets, const float* __restrict__ segsum,
    float* __restrict__ out, int nseg)
{
    __shared__ int   sh_r[128];
    __shared__ float sh_w[128];
    const int s = blockIdx.x;
    if (s >= nseg) return;
    const int d = threadIdx.x;
    const int beg = offsets[s];
    const int end = offsets[s + 1];
    float acc = 0.f;
    for (int cb = beg; cb < end; cb += 128) {
        const int m = min(128, end - cb);
        if (d < m) {
            sh_r[d] = rows[cb + d];
            sh_w[d] = ew[cb + d];
        }
        __syncthreads();
        float p0 = 0.f, p1 = 0.f, p2 = 0.f, p3 = 0.f;
        int j = 0;
        for (; j + 4 <= m; j += 4) {
            p0 += sh_w[j]     * vmat[(size_t)sh_r[j]     * vstride + voff + d];
            p1 += sh_w[j + 1] * vmat[(size_t)sh_r[j + 1] * vstride + voff + d];
            p2 += sh_w[j + 2] * vmat[(size_t)sh_r[j + 2] * vstride + voff + d];
            p3 += sh_w[j + 3] * vmat[(size_t)sh_r[j + 3] * vstride + voff + d];
        }
        for (; j < m; j++)
            p0 += sh_w[j] * vmat[(size_t)sh_r[j] * vstride + voff + d];
        acc += (p0 + p1) + (p2 + p3);
        __syncthreads();
    }
    out[(size_t)s * 256 + d] = fmaxf(acc / fmaxf(segsum[s], 1e-20f), 0.f);
}

// ---------------------------------------------------------------------------
// Launch
// ---------------------------------------------------------------------------
extern "C" void kernel_launch(void* const* d_in, const int* in_sizes, int n_in,
                              void* d_out, int out_size)
{
    const float* vfeat    = (const float*)d_in[0];
    const float* efeat    = (const float*)d_in[1];
    const int*   node_idx = (const int*)d_in[2];
    const int*   edge_idx = (const int*)d_in[3];
    const float* W_vtx = (const float*)d_in[4];  const float* b_vtx = (const float*)d_in[5];
    const float* W_qe  = (const float*)d_in[6];  const float* b_qe  = (const float*)d_in[7];
    const float* W_kv  = (const float*)d_in[8];  const float* b_kv  = (const float*)d_in[9];
    const float* W_vv  = (const float*)d_in[10]; const float* b_vv  = (const float*)d_in[11];
    const float* W_qv  = (const float*)d_in[12]; const float* b_qv  = (const float*)d_in[13];
    const float* W_ke  = (const float*)d_in[14]; const float* b_ke  = (const float*)d_in[15];
    const float* W_ve  = (const float*)d_in[16]; const float* b_ve  = (const float*)d_in[17];

    float* out_v = (float*)d_out;
    float* out_e = out_v + (size_t)N_NODES * VDIM;

    float *fused1, *fused2, *q1, *Wcomb, *bcomb, *Wcat2, *bcat2;
    float *ss_e, *ss_n, *ew;
    int *cnt_e, *cnt_n, *off_e, *off_n, *cur_e, *cur_n, *rows, *partials;
    cudaGetSymbolAddress((void**)&fused1, g_fused1);
    cudaGetSymbolAddress((void**)&fused2, g_fused2);
    cudaGetSymbolAddress((void**)&q1, g_q1);
    cudaGetSymbolAddress((void**)&Wcomb, g_Wcomb);
    cudaGetSymbolAddress((void**)&bcomb, g_bcomb);
    cudaGetSymbolAddress((void**)&Wcat2, g_Wcat2);
    cudaGetSymbolAddress((void**)&bcat2, g_bcat2);
    cudaGetSymbolAddress((void**)&cnt_e, g_cnt_e);
    cudaGetSymbolAddress((void**)&cnt_n, g_cnt_n);
    cudaGetSymbolAddress((void**)&off_e, g_off_e);
    cudaGetSymbolAddress((void**)&off_n, g_off_n);
    cudaGetSymbolAddress((void**)&cur_e, g_cur_e);
    cudaGetSymbolAddress((void**)&cur_n, g_cur_n);
    cudaGetSymbolAddress((void**)&ss_e, g_segsum_e);
    cudaGetSymbolAddress((void**)&ss_n, g_segsum_n);
    cudaGetSymbolAddress((void**)&rows, g_rows);
    cudaGetSymbolAddress((void**)&ew, g_ew);
    cudaGetSymbolAddress((void**)&partials, g_partials);

    const int nnzBlocks   = (NNZ + 255) / 256;
    const int scoreBlocks = (NNZ * 32 + 255) / 256;

    // ---- weight pre-combination + concat ----
    combine_w_kernel<<<F1W / 8, 256>>>(W_kv, W_vv, W_qv, W_vtx, Wcomb);
    combine_b_kernel<<<2, 256>>>(W_kv, W_vv, W_qv, b_kv, b_vv, b_qv, b_vtx, bcomb);
    cudaMemcpyAsync(Wcat2,             W_ke, (size_t)QDIM * EDIM * 4, cudaMemcpyDeviceToDevice);
    cudaMemcpyAsync(Wcat2 + 128 * 256, W_ve, (size_t)VDIM * EDIM * 4, cudaMemcpyDeviceToDevice);
    cudaMemcpyAsync(bcat2,       b_ke, QDIM * 4, cudaMemcpyDeviceToDevice);
    cudaMemcpyAsync(bcat2 + 128, b_ve, VDIM * 4, cudaMemcpyDeviceToDevice);

    // ---- upfront CSR build for both passes ----
    init_dual_kernel<<<(N_NODES + 255) / 256, 256>>>(cnt_e, cnt_n, ss_e, ss_n);
    hist_dual_kernel<<<nnzBlocks, 256>>>(edge_idx, node_idx, cnt_e, cnt_n, NNZ);
    scan_dual_block_kernel<<<NB_E + NB_N, 1024>>>(cnt_e, off_e, cnt_n, off_n, partials);
    scan_serial_kernel<<<1, 32>>>(partials, off_e, off_n);
    scan_add_dual_kernel<<<(N_NODES + 255) / 256, 256>>>(off_e, cur_e, off_n, cur_n, partials);

    // ---- projections: fused1 (k1|v1|q2) + q1 in ONE launch ----
    {
        const int nb0 = (F1W / BN) * ((N_NODES + BM - 1) / BM);   // 8 * 391
        const int nb1 = (QDIM / BN) * ((N_EDGES + BM - 1) / BM);  // 2 * 79
        gemm_dual_kernel<<<nb0 + nb1, 256>>>(
            vfeat, Wcomb, bcomb, fused1, N_NODES, F1W,
            efeat, W_qe,  b_qe,  q1,     N_EDGES, QDIM,
            KIN, nb0);
    }

    // ---- pass 1: nodes -> hyperedges ----
    score_fused_kernel<<<scoreBlocks, 256>>>(fused1, F1W, q1, QDIM,
                                             node_idx, edge_idx,
                                             ss_e, cur_e, rows, ew, NNZ);
    aggregate_kernel<<<N_EDGES, 256>>>(fused1, F1W, 128, rows, ew,
                                       off_e, ss_e, out_e, N_EDGES);

    // ---- edge-side fused projection (k2|v2) ----
    run_gemm:
    gemm_bf16_kernel<<<dim3(F2W / BN, (N_EDGES + BM - 1) / BM), 256>>>(
        out_e, Wcat2, bcat2, fused2, N_EDGES, F2W, EDIM);

    // ---- pass 2: hyperedges -> nodes ----
    score_fused_kernel<<<scoreBlocks, 256>>>(fused2, F2W, fused1 + 384, F1W,
                                             edge_idx, node_idx,
                                             ss_n, cur_n, rows, ew, NNZ);
    aggregate_kernel<<<N_NODES, 256>>>(fused2, F2W, 128, rows, ew,
                                       off_n, ss_n, out_v, N_NODES);
}

// round 14
// speedup vs baseline: 1.1771x; 1.1199x over previous
#include <cuda_runtime.h>
#include <cuda_bf16.h>
#include <math.h>
#include <stdint.h>

// ---------------------------------------------------------------------------
// Problem constants
// ---------------------------------------------------------------------------
#define N_NODES 50000
#define N_EDGES 10000
#define NNZ     400000
#define QDIM    128
#define VDIM    256
#define EDIM    256
#define KIN     256
#define NEG_SLOPE 0.01f
#define SCORE_SCALE 0.08838834764831845f   // 1/sqrt(128)

#define F1W 256   // k1 | q2   (v1 eliminated via projection-commute trick)
#define F2W 384   // k2 | v2

// ---------------------------------------------------------------------------
// Static scratch
// ---------------------------------------------------------------------------
__device__ float g_fused1[N_NODES * F1W];
__device__ float g_fused2[N_EDGES * F2W];
__device__ float g_q1[N_EDGES * QDIM];
__device__ float g_agg1[N_EDGES * 256];
__device__ float g_Wcomb[512 * KIN];     // rows: kvc(0-127) | qvc(128-255) | vvc(256-511)
__device__ float g_bcomb[512];
__device__ float g_Wcat2[F2W * EDIM];
__device__ float g_bcat2[F2W];
__device__ int   g_cnt_e[N_EDGES];
__device__ int   g_cnt_n[N_NODES];
__device__ int   g_off_e[N_EDGES + 1];
__device__ int   g_off_n[N_NODES + 1];
__device__ int   g_cur_e[N_EDGES];
__device__ int   g_cur_n[N_NODES];
__device__ float g_segsum_e[N_EDGES];
__device__ float g_segsum_n[N_NODES];
__device__ int   g_rows[NNZ];
__device__ float g_ew[NNZ];
__device__ int   g_partials[80];

// ---------------------------------------------------------------------------
// Weight pre-combination: row o of Wcomb = (Wsel row) @ Wvtx
// layout: o in [0,128)=W_kv, [128,256)=W_qv, [256,512)=W_vv
// ---------------------------------------------------------------------------
__device__ __forceinline__ const float* comb_src(
    int o, const float* Wkv, const float* Wqv, const float* Wvv)
{
    return (o < 128) ? Wkv + (size_t)o * 256
         : (o < 256) ? Wqv + (size_t)(o - 128) * 256
                     : Wvv + (size_t)(o - 256) * 256;
}

__global__ __launch_bounds__(256) void combine_w_kernel(
    const float* __restrict__ Wkv, const float* __restrict__ Wqv,
    const float* __restrict__ Wvv, const float* __restrict__ Wvtx,
    float* __restrict__ Wcomb)
{
    __shared__ float a[8][256];
    const int ob = blockIdx.x * 8;
    const int i = threadIdx.x;
#pragma unroll
    for (int r = 0; r < 8; r++)
        a[r][i] = comb_src(ob + r, Wkv, Wqv, Wvv)[i];
    __syncthreads();
    float s[8];
#pragma unroll
    for (int r = 0; r < 8; r++) s[r] = 0.f;
    for (int v = 0; v < 256; v++) {
        const float w = Wvtx[(size_t)v * 256 + i];
#pragma unroll
        for (int r = 0; r < 8; r++) s[r] += a[r][v] * w;
    }
#pragma unroll
    for (int r = 0; r < 8; r++) Wcomb[(size_t)(ob + r) * 256 + i] = s[r];
}

__global__ void combine_b_kernel(
    const float* __restrict__ Wkv, const float* __restrict__ Wqv,
    const float* __restrict__ Wvv,
    const float* __restrict__ bkv, const float* __restrict__ bqv,
    const float* __restrict__ bvv, const float* __restrict__ bvtx,
    float* __restrict__ bcomb)
{
    const int o = blockIdx.x * blockDim.x + threadIdx.x;
    if (o >= 512) return;
    const float* wsrc = comb_src(o, Wkv, Wqv, Wvv);
    float b = (o < 128) ? bkv[o] : (o < 256) ? bqv[o - 128] : bvv[o - 256];
    float s = b;
    for (int v = 0; v < 256; v++) s += wsrc[v] * bvtx[v];
    bcomb[o] = s;
}

// ---------------------------------------------------------------------------
// bf16-split tensor-core GEMM body (proven inner loop).
// epilogue: if ss != nullptr -> relu, and zero row when ss[m]==0 (empty seg).
// ---------------------------------------------------------------------------
#define BM 128
#define BN 64
#define BK 32
#define SS2 20

__device__ __forceinline__ void mma_bf16(float* c,
    uint32_t a0, uint32_t a1, uint32_t a2, uint32_t a3,
    uint32_t b0, uint32_t b1)
{
    asm volatile(
        "mma.sync.aligned.m16n8k16.row.col.f32.bf16.bf16.f32 "
        "{%0,%1,%2,%3}, {%4,%5,%6,%7}, {%8,%9}, {%0,%1,%2,%3};"
        : "+f"(c[0]), "+f"(c[1]), "+f"(c[2]), "+f"(c[3])
        : "r"(a0), "r"(a1), "r"(a2), "r"(a3), "r"(b0), "r"(b1));
}

__device__ __forceinline__ uint2 split2(float x0, float x1)
{
    __nv_bfloat16 h0 = __float2bfloat16_rn(x0);
    __nv_bfloat16 h1 = __float2bfloat16_rn(x1);
    __nv_bfloat16 l0 = __float2bfloat16_rn(x0 - __bfloat162float(h0));
    __nv_bfloat16 l1 = __float2bfloat16_rn(x1 - __bfloat162float(h1));
    uint2 r;
    r.x = (uint32_t)__bfloat16_as_ushort(h0) | ((uint32_t)__bfloat16_as_ushort(h1) << 16);
    r.y = (uint32_t)__bfloat16_as_ushort(l0) | ((uint32_t)__bfloat16_as_ushort(l1) << 16);
    return r;
}

__device__ __forceinline__ void gemm_body(
    const float* __restrict__ A, const float* __restrict__ W,
    const float* __restrict__ bias, float* __restrict__ C,
    int M, int N, int K, int bxx, int byy, const float* __restrict__ ss)
{
    __shared__ uint2 As2[BM][SS2];
    __shared__ uint2 Bs2[BN][SS2];

    const int t    = threadIdx.x;
    const int lane = t & 31;
    const int wid  = t >> 5;
    const int wm   = wid & 3;
    const int wn   = wid >> 2;
    const int g    = lane >> 2;
    const int t4   = lane & 3;

    const int block_m = byy * BM;
    const int block_n = bxx * BN;

    const int arow_i = t >> 1;
    const int aseg   = (t & 1) * 16;
    const int brow_i = t >> 2;
    const int bseg   = (t & 3) * 8;
    const int gma = block_m + arow_i;
    const float* aptr = A + (size_t)(gma < M ? gma : (M - 1)) * K + aseg;
    const float* bptr = W + (size_t)(block_n + brow_i) * K + bseg;

    float acc[2][4][4];
#pragma unroll
    for (int i = 0; i < 2; i++)
#pragma unroll
        for (int j = 0; j < 4; j++)
#pragma unroll
            for (int l = 0; l < 4; l++) acc[i][j][l] = 0.f;

    float4 pa[4], pb[2];
#pragma unroll
    for (int u = 0; u < 4; u++) pa[u] = *(const float4*)(aptr + u * 4);
#pragma unroll
    for (int u = 0; u < 2; u++) pb[u] = *(const float4*)(bptr + u * 4);

    const int NC = K / BK;
    for (int c = 0; c < NC; c++) {
#pragma unroll
        for (int u = 0; u < 4; u++) {
            uint2 p0 = split2(pa[u].x, pa[u].y);
            uint2 p1 = split2(pa[u].z, pa[u].w);
            asm volatile("st.shared.v4.b32 [%0], {%1,%2,%3,%4};" ::
                "l"(__cvta_generic_to_shared(&As2[arow_i][aseg / 2 + u * 2])),
                "r"(p0.x), "r"(p0.y), "r"(p1.x), "r"(p1.y) : "memory");
        }
#pragma unroll
        for (int u = 0; u < 2; u++) {
            uint2 p0 = split2(pb[u].x, pb[u].y);
            uint2 p1 = split2(pb[u].z, pb[u].w);
            asm volatile("st.shared.v4.b32 [%0], {%1,%2,%3,%4};" ::
                "l"(__cvta_generic_to_shared(&Bs2[brow_i][bseg / 2 + u * 2])),
                "r"(p0.x), "r"(p0.y), "r"(p1.x), "r"(p1.y) : "memory");
        }
        __syncthreads();

        if (c + 1 < NC) {
            const int k1o = (c + 1) * BK;
#pragma unroll
            for (int u = 0; u < 4; u++) pa[u] = *(const float4*)(aptr + k1o + u * 4);
#pragma unroll
            for (int u = 0; u < 2; u++) pb[u] = *(const float4*)(bptr + k1o + u * 4);
        }

#pragma unroll
        for (int kk = 0; kk < 2; kk++) {
            const int kc0 = kk * 8 + t4;
            const int kc1 = kc0 + 4;
            uint32_t ahi[2][4], alo[2][4];
#pragma unroll
            for (int mt = 0; mt < 2; mt++) {
                const int r0 = wm * 32 + mt * 16 + g;
                uint2 v0 = As2[r0][kc0];
                uint2 v1 = As2[r0 + 8][kc0];
                uint2 v2 = As2[r0][kc1];
                uint2 v3 = As2[r0 + 8][kc1];
                ahi[mt][0] = v0.x; alo[mt][0] = v0.y;
                ahi[mt][1] = v1.x; alo[mt][1] = v1.y;
                ahi[mt][2] = v2.x; alo[mt][2] = v2.y;
                ahi[mt][3] = v3.x; alo[mt][3] = v3.y;
            }
            uint32_t bhi[4][2], blo[4][2];
#pragma unroll
            for (int nt = 0; nt < 4; nt++) {
                const int n0 = wn * 32 + nt * 8 + g;
                uint2 u0 = Bs2[n0][kc0];
                uint2 u1 = Bs2[n0][kc1];
                bhi[nt][0] = u0.x; blo[nt][0] = u0.y;
                bhi[nt][1] = u1.x; blo[nt][1] = u1.y;
            }
#pragma unroll
            for (int mt = 0; mt < 2; mt++)
#pragma unroll
                for (int nt = 0; nt < 4; nt++)
                    mma_bf16(acc[mt][nt], ahi[mt][0], ahi[mt][1], ahi[mt][2], ahi[mt][3],
                             bhi[nt][0], bhi[nt][1]);
#pragma unroll
            for (int mt = 0; mt < 2; mt++)
#pragma unroll
                for (int nt = 0; nt < 4; nt++)
                    mma_bf16(acc[mt][nt], ahi[mt][0], ahi[mt][1], ahi[mt][2], ahi[mt][3],
                             blo[nt][0], blo[nt][1]);
#pragma unroll
            for (int mt = 0; mt < 2; mt++)
#pragma unroll
                for (int nt = 0; nt < 4; nt++)
                    mma_bf16(acc[mt][nt], alo[mt][0], alo[mt][1], alo[mt][2], alo[mt][3],
                             bhi[nt][0], bhi[nt][1]);
        }
        __syncthreads();
    }

#pragma unroll
    for (int mt = 0; mt < 2; mt++) {
#pragma unroll
        for (int nt = 0; nt < 4; nt++) {
            const int m0 = block_m + wm * 32 + mt * 16 + g;
            const int n0 = block_n + wn * 32 + nt * 8 + t4 * 2;
            const float bv0 = bias[n0], bv1 = bias[n0 + 1];
#pragma unroll
            for (int h = 0; h < 2; h++) {
                const int m = m0 + h * 8;
                if (m < M) {
                    float o0 = acc[mt][nt][h * 2]     + bv0;
                    float o1 = acc[mt][nt][h * 2 + 1] + bv1;
                    if (ss) {
                        const float alive = (ss[m] != 0.f) ? 1.f : 0.f;
                        o0 = fmaxf(o0, 0.f) * alive;
                        o1 = fmaxf(o1, 0.f) * alive;
                    }
                    *(float2*)&C[(size_t)m * N + n0] = make_float2(o0, o1);
                }
            }
        }
    }
}

__global__ __launch_bounds__(256, 2) void gemm_bf16_kernel(
    const float* __restrict__ A, const float* __restrict__ W,
    const float* __restrict__ bias, float* __restrict__ C,
    int M, int N, int K, const float* __restrict__ ss)
{
    gemm_body(A, W, bias, C, M, N, K, blockIdx.x, blockIdx.y, ss);
}

__global__ __launch_bounds__(256, 2) void gemm_dual_kernel(
    const float* __restrict__ A0, const float* __restrict__ W0,
    const float* __restrict__ b0, float* __restrict__ C0, int M0, int N0,
    const float* __restrict__ A1, const float* __restrict__ W1,
    const float* __restrict__ b1, float* __restrict__ C1, int M1, int N1,
    int K, int nb0)
{
    int b = blockIdx.x;
    if (b < nb0) {
        const int gx = N0 / BN;
        gemm_body(A0, W0, b0, C0, M0, N0, K, b % gx, b / gx, nullptr);
    } else {
        b -= nb0;
        const int gx = N1 / BN;
        gemm_body(A1, W1, b1, C1, M1, N1, K, b % gx, b / gx, nullptr);
    }
}

// ---------------------------------------------------------------------------
// Upfront CSR build for BOTH passes
// ---------------------------------------------------------------------------
__global__ void init_dual_kernel(int* cnt_e, int* cnt_n, float* ss_e, float* ss_n)
{
    int i = blockIdx.x * blockDim.x + threadIdx.x;
    if (i < N_EDGES) { cnt_e[i] = 0; ss_e[i] = 0.f; }
    if (i < N_NODES) { cnt_n[i] = 0; ss_n[i] = 0.f; }
}

__global__ void hist_dual_kernel(const int* __restrict__ eidx, const int* __restrict__ nidx,
                                 int* __restrict__ cnt_e, int* __restrict__ cnt_n, int nnz)
{
    int i = blockIdx.x * blockDim.x + threadIdx.x;
    if (i < nnz) {
        atomicAdd(&cnt_e[eidx[i]], 1);
        atomicAdd(&cnt_n[nidx[i]], 1);
    }
}

__device__ __forceinline__ void scan_block_body(
    const int* counts, int* offsets, int* partials, int n, int blk)
{
    __shared__ int sh[1024];
    const int t = threadIdx.x;
    const int i = blk * 1024 + t;
    const int x = (i < n) ? counts[i] : 0;
    sh[t] = x;
    __syncthreads();
    for (int off = 1; off < 1024; off <<= 1) {
        int v = (t >= off) ? sh[t - off] : 0;
        __syncthreads();
        sh[t] += v;
        __syncthreads();
    }
    if (i < n) offsets[i] = sh[t] - x;
    if (t == 1023) partials[blk] = sh[1023];
}

#define NB_E ((N_EDGES + 1023) / 1024)   // 10
#define NB_N ((N_NODES + 1023) / 1024)   // 49

__global__ __launch_bounds__(1024) void scan_dual_block_kernel(
    const int* cnt_e, int* off_e, const int* cnt_n, int* off_n, int* partials)
{
    const int b = blockIdx.x;
    if (b < NB_E) scan_block_body(cnt_e, off_e, partials, N_EDGES, b);
    else          scan_block_body(cnt_n, off_n, partials + 16, N_NODES, b - NB_E);
}

__global__ void scan_serial_kernel(int* partials, int* off_e, int* off_n)
{
    if (threadIdx.x == 0) {
        int run = 0;
        for (int i = 0; i < NB_E; i++) { int t = partials[i]; partials[i] = run; run += t; }
        off_e[N_EDGES] = NNZ;
    } else if (threadIdx.x == 1) {
        int run = 0;
        for (int i = 0; i < NB_N; i++) { int t = partials[16 + i]; partials[16 + i] = run; run += t; }
        off_n[N_NODES] = NNZ;
    }
}

__global__ void scan_add_dual_kernel(int* off_e, int* cur_e, int* off_n, int* cur_n,
                                     const int* partials)
{
    int i = blockIdx.x * blockDim.x + threadIdx.x;
    if (i < N_EDGES) {
        int v = off_e[i] + partials[i >> 10];
        off_e[i] = v;
        cur_e[i] = v;
    }
    if (i < N_NODES) {
        int v = off_n[i] + partials[16 + (i >> 10)];
        off_n[i] = v;
        cur_n[i] = v;
    }
}

// ---------------------------------------------------------------------------
// Fused score+exp+scatter: warp per nnz (no segmax; scores are O(1))
// ---------------------------------------------------------------------------
__global__ __launch_bounds__(256) void score_fused_kernel(
    const float* __restrict__ kmat, int kstride,
    const float* __restrict__ qmat, int qstride,
    const int* __restrict__ kidx, const int* __restrict__ seg,
    float* __restrict__ segsum, int* __restrict__ cursor,
    int* __restrict__ rows, float* __restrict__ ew, int nnz)
{
    const int w = (blockIdx.x * blockDim.x + threadIdx.x) >> 5;
    const int lane = threadIdx.x & 31;
    if (w >= nnz) return;
    const int ki = kidx[w];
    const int sg = seg[w];
    float4 a = *(const float4*)&kmat[(size_t)ki * kstride + lane * 4];
    float4 b = *(const float4*)&qmat[(size_t)sg * qstride + lane * 4];
    float d = a.x * b.x + a.y * b.y + a.z * b.z + a.w * b.w;
#pragma unroll
    for (int o = 16; o > 0; o >>= 1) d += __shfl_xor_sync(0xffffffffu, d, o);
    if (lane == 0) {
        const float s = (d >= 0.f ? d : NEG_SLOPE * d) * SCORE_SCALE;
        const float e = __expf(s);
        atomicAdd(&segsum[sg], e);
        const int pos = atomicAdd(&cursor[sg], 1);
        rows[pos] = ki;
        ew[pos] = e;
    }
}

// ---------------------------------------------------------------------------
// Aggregate: one block/segment, 256 threads = 256 dims; RELU optional.
// ---------------------------------------------------------------------------
template <bool RELU>
__global__ __launch_bounds__(256) void aggregate_kernel(
    const float* __restrict__ vmat, int vstride, int voff,
    const int* __restrict__ rows, const float* __restrict__ ew,
    const int* __restrict__ offsets, const float* __restrict__ segsum,
    float* __restrict__ out, int nseg)
{
    __shared__ int   sh_r[128];
    __shared__ float sh_w[128];
    const int s = blockIdx.x;
    if (s >= nseg) return;
    const int d = threadIdx.x;
    const int beg = offsets[s];
    const int end = offsets[s + 1];
    float acc = 0.f;
    for (int cb = beg; cb < end; cb += 128) {
        const int m = min(128, end - cb);
        if (d < m) {
            sh_r[d] = rows[cb + d];
            sh_w[d] = ew[cb + d];
        }
        __syncthreads();
        float p0 = 0.f, p1 = 0.f, p2 = 0.f, p3 = 0.f;
        int j = 0;
        for (; j + 4 <= m; j += 4) {
            p0 += sh_w[j]     * vmat[(size_t)sh_r[j]     * vstride + voff + d];
            p1 += sh_w[j + 1] * vmat[(size_t)sh_r[j + 1] * vstride + voff + d];
            p2 += sh_w[j + 2] * vmat[(size_t)sh_r[j + 2] * vstride + voff + d];
            p3 += sh_w[j + 3] * vmat[(size_t)sh_r[j + 3] * vstride + voff + d];
        }
        for (; j < m; j++)
            p0 += sh_w[j] * vmat[(size_t)sh_r[j] * vstride + voff + d];
        acc += (p0 + p1) + (p2 + p3);
        __syncthreads();
    }
    float r = acc / fmaxf(segsum[s], 1e-20f);
    if (RELU) r = fmaxf(r, 0.f);
    out[(size_t)s * 256 + d] = r;
}

// ---------------------------------------------------------------------------
// Launch
// ---------------------------------------------------------------------------
extern "C" void kernel_launch(void* const* d_in, const int* in_sizes, int n_in,
                              void* d_out, int out_size)
{
    const float* vfeat    = (const float*)d_in[0];
    const float* efeat    = (const float*)d_in[1];
    const int*   node_idx = (const int*)d_in[2];
    const int*   edge_idx = (const int*)d_in[3];
    const float* W_vtx = (const float*)d_in[4];  const float* b_vtx = (const float*)d_in[5];
    const float* W_qe  = (const float*)d_in[6];  const float* b_qe  = (const float*)d_in[7];
    const float* W_kv  = (const float*)d_in[8];  const float* b_kv  = (const float*)d_in[9];
    const float* W_vv  = (const float*)d_in[10]; const float* b_vv  = (const float*)d_in[11];
    const float* W_qv  = (const float*)d_in[12]; const float* b_qv  = (const float*)d_in[13];
    const float* W_ke  = (const float*)d_in[14]; const float* b_ke  = (const float*)d_in[15];
    const float* W_ve  = (const float*)d_in[16]; const float* b_ve  = (const float*)d_in[17];

    float* out_v = (float*)d_out;
    float* out_e = out_v + (size_t)N_NODES * VDIM;

    float *fused1, *fused2, *q1, *agg1, *Wcomb, *bcomb, *Wcat2, *bcat2;
    float *ss_e, *ss_n, *ew;
    int *cnt_e, *cnt_n, *off_e, *off_n, *cur_e, *cur_n, *rows, *partials;
    cudaGetSymbolAddress((void**)&fused1, g_fused1);
    cudaGetSymbolAddress((void**)&fused2, g_fused2);
    cudaGetSymbolAddress((void**)&q1, g_q1);
    cudaGetSymbolAddress((void**)&agg1, g_agg1);
    cudaGetSymbolAddress((void**)&Wcomb, g_Wcomb);
    cudaGetSymbolAddress((void**)&bcomb, g_bcomb);
    cudaGetSymbolAddress((void**)&Wcat2, g_Wcat2);
    cudaGetSymbolAddress((void**)&bcat2, g_bcat2);
    cudaGetSymbolAddress((void**)&cnt_e, g_cnt_e);
    cudaGetSymbolAddress((void**)&cnt_n, g_cnt_n);
    cudaGetSymbolAddress((void**)&off_e, g_off_e);
    cudaGetSymbolAddress((void**)&off_n, g_off_n);
    cudaGetSymbolAddress((void**)&cur_e, g_cur_e);
    cudaGetSymbolAddress((void**)&cur_n, g_cur_n);
    cudaGetSymbolAddress((void**)&ss_e, g_segsum_e);
    cudaGetSymbolAddress((void**)&ss_n, g_segsum_n);
    cudaGetSymbolAddress((void**)&rows, g_rows);
    cudaGetSymbolAddress((void**)&ew, g_ew);
    cudaGetSymbolAddress((void**)&partials, g_partials);

    const int nnzBlocks   = (NNZ + 255) / 256;
    const int scoreBlocks = (NNZ * 32 + 255) / 256;

    // ---- weight pre-combination + concat ----
    combine_w_kernel<<<512 / 8, 256>>>(W_kv, W_qv, W_vv, W_vtx, Wcomb);
    combine_b_kernel<<<2, 256>>>(W_kv, W_qv, W_vv, b_kv, b_qv, b_vv, b_vtx, bcomb);
    cudaMemcpyAsync(Wcat2,             W_ke, (size_t)QDIM * EDIM * 4, cudaMemcpyDeviceToDevice);
    cudaMemcpyAsync(Wcat2 + 128 * 256, W_ve, (size_t)VDIM * EDIM * 4, cudaMemcpyDeviceToDevice);
    cudaMemcpyAsync(bcat2,       b_ke, QDIM * 4, cudaMemcpyDeviceToDevice);
    cudaMemcpyAsync(bcat2 + 128, b_ve, VDIM * 4, cudaMemcpyDeviceToDevice);

    // ---- upfront CSR build for both passes ----
    init_dual_kernel<<<(N_NODES + 255) / 256, 256>>>(cnt_e, cnt_n, ss_e, ss_n);
    hist_dual_kernel<<<nnzBlocks, 256>>>(edge_idx, node_idx, cnt_e, cnt_n, NNZ);
    scan_dual_block_kernel<<<NB_E + NB_N, 1024>>>(cnt_e, off_e, cnt_n, off_n, partials);
    scan_serial_kernel<<<1, 32>>>(partials, off_e, off_n);
    scan_add_dual_kernel<<<(N_NODES + 255) / 256, 256>>>(off_e, cur_e, off_n, cur_n, partials);

    // ---- projections: fused1 (k1|q2, 256-wide) + q1 in one launch ----
    {
        const int nb0 = (F1W / BN) * ((N_NODES + BM - 1) / BM);   // 4 * 391
        const int nb1 = (QDIM / BN) * ((N_EDGES + BM - 1) / BM);  // 2 * 79
        gemm_dual_kernel<<<nb0 + nb1, 256>>>(
            vfeat, Wcomb, bcomb, fused1, N_NODES, F1W,
            efeat, W_qe,  b_qe,  q1,     N_EDGES, QDIM,
            KIN, nb0);
    }

    // ---- pass 1: nodes -> hyperedges ----
    score_fused_kernel<<<scoreBlocks, 256>>>(fused1, F1W, q1, QDIM,
                                             node_idx, edge_idx,
                                             ss_e, cur_e, rows, ew, NNZ);
    // aggregate RAW vfeat rows (projection-commute trick), no relu
    aggregate_kernel<false><<<N_EDGES, 256>>>(vfeat, KIN, 0, rows, ew,
                                              off_e, ss_e, agg1, N_EDGES);
    // post-GEMM: out_e = relu(agg1 @ Wvvc^T + bvvc), zero where segment empty
    gemm_bf16_kernel<<<dim3(256 / BN, (N_EDGES + BM - 1) / BM), 256>>>(
        agg1, Wcomb + 256 * 256, bcomb + 256, out_e, N_EDGES, 256, 256, ss_e);

    // ---- edge-side fused projection (k2|v2) ----
    gemm_bf16_kernel<<<dim3(F2W / BN, (N_EDGES + BM - 1) / BM), 256>>>(
        out_e, Wcat2, bcat2, fused2, N_EDGES, F2W, EDIM, nullptr);

    // ---- pass 2: hyperedges -> nodes ----
    score_fused_kernel<<<scoreBlocks, 256>>>(fused2, F2W, fused1 + 128, F1W,
                                             edge_idx, node_idx,
                                             ss_n, cur_n, rows, ew, NNZ);
    aggregate_kernel<true><<<N_NODES, 256>>>(fused2, F2W, 128, rows, ew,
                                             off_n, ss_n, out_v, N_NODES);
}

// round 16
// speedup vs baseline: 1.2004x; 1.0198x over previous
#include <cuda_runtime.h>
#include <cuda_bf16.h>
#include <math.h>
#include <stdint.h>

// ---------------------------------------------------------------------------
// Problem constants
// ---------------------------------------------------------------------------
#define N_NODES 50000
#define N_EDGES 10000
#define NNZ     400000
#define QDIM    128
#define VDIM    256
#define EDIM    256
#define KIN     256
#define NEG_SLOPE 0.01f
#define SCORE_SCALE 0.08838834764831845f   // 1/sqrt(128)

#define F1W 256   // k1 | q2   (v1 eliminated via projection-commute trick)
#define F2W 384   // k2 | v2

// ---------------------------------------------------------------------------
// Static scratch
// ---------------------------------------------------------------------------
__device__ float g_fused1[N_NODES * F1W];
__device__ float g_fused2[N_EDGES * F2W];
__device__ float g_q1[N_EDGES * QDIM];
__device__ float g_agg1[N_EDGES * 256];
__device__ float g_Wcomb[512 * KIN];     // rows: kvc(0-127) | qvc(128-255) | vvc(256-511)
__device__ float g_bcomb[512];
__device__ float g_Wcat2[F2W * EDIM];
__device__ float g_bcat2[F2W];
__device__ int   g_cnt_e[N_EDGES];
__device__ int   g_cnt_n[N_NODES];
__device__ int   g_off_e[N_EDGES + 1];
__device__ int   g_off_n[N_NODES + 1];
__device__ int   g_cur_e[N_EDGES];
__device__ int   g_cur_n[N_NODES];
__device__ float g_segsum_e[N_EDGES];
__device__ int   g_rows_e[NNZ];          // pass-1 CSR: node rows grouped by edge
__device__ int   g_rows_n[NNZ];          // pass-2 CSR: edge rows grouped by node
__device__ int   g_partials[80];

// ---------------------------------------------------------------------------
// Weight pre-combination: row o of Wcomb = (Wsel row) @ Wvtx
// layout: o in [0,128)=W_kv, [128,256)=W_qv, [256,512)=W_vv
// ---------------------------------------------------------------------------
__device__ __forceinline__ const float* comb_src(
    int o, const float* Wkv, const float* Wqv, const float* Wvv)
{
    return (o < 128) ? Wkv + (size_t)o * 256
         : (o < 256) ? Wqv + (size_t)(o - 128) * 256
                     : Wvv + (size_t)(o - 256) * 256;
}

__global__ __launch_bounds__(256) void combine_w_kernel(
    const float* __restrict__ Wkv, const float* __restrict__ Wqv,
    const float* __restrict__ Wvv, const float* __restrict__ Wvtx,
    float* __restrict__ Wcomb)
{
    __shared__ float a[8][256];
    const int ob = blockIdx.x * 8;
    const int i = threadIdx.x;
#pragma unroll
    for (int r = 0; r < 8; r++)
        a[r][i] = comb_src(ob + r, Wkv, Wqv, Wvv)[i];
    __syncthreads();
    float s[8];
#pragma unroll
    for (int r = 0; r < 8; r++) s[r] = 0.f;
    for (int v = 0; v < 256; v++) {
        const float w = Wvtx[(size_t)v * 256 + i];
#pragma unroll
        for (int r = 0; r < 8; r++) s[r] += a[r][v] * w;
    }
#pragma unroll
    for (int r = 0; r < 8; r++) Wcomb[(size_t)(ob + r) * 256 + i] = s[r];
}

__global__ void combine_b_kernel(
    const float* __restrict__ Wkv, const float* __restrict__ Wqv,
    const float* __restrict__ Wvv,
    const float* __restrict__ bkv, const float* __restrict__ bqv,
    const float* __restrict__ bvv, const float* __restrict__ bvtx,
    float* __restrict__ bcomb)
{
    const int o = blockIdx.x * blockDim.x + threadIdx.x;
    if (o >= 512) return;
    const float* wsrc = comb_src(o, Wkv, Wqv, Wvv);
    float b = (o < 128) ? bkv[o] : (o < 256) ? bqv[o - 128] : bvv[o - 256];
    float s = b;
    for (int v = 0; v < 256; v++) s += wsrc[v] * bvtx[v];
    bcomb[o] = s;
}

// ---------------------------------------------------------------------------
// bf16-split tensor-core GEMM body (proven inner loop).
// epilogue: if ss != nullptr -> relu, and zero row when ss[m]==0 (empty seg).
// ---------------------------------------------------------------------------
#define BM 128
#define BN 64
#define BK 32
#define SS2 20

__device__ __forceinline__ void mma_bf16(float* c,
    uint32_t a0, uint32_t a1, uint32_t a2, uint32_t a3,
    uint32_t b0, uint32_t b1)
{
    asm volatile(
        "mma.sync.aligned.m16n8k16.row.col.f32.bf16.bf16.f32 "
        "{%0,%1,%2,%3}, {%4,%5,%6,%7}, {%8,%9}, {%0,%1,%2,%3};"
        : "+f"(c[0]), "+f"(c[1]), "+f"(c[2]), "+f"(c[3])
        : "r"(a0), "r"(a1), "r"(a2), "r"(a3), "r"(b0), "r"(b1));
}

__device__ __forceinline__ uint2 split2(float x0, float x1)
{
    __nv_bfloat16 h0 = __float2bfloat16_rn(x0);
    __nv_bfloat16 h1 = __float2bfloat16_rn(x1);
    __nv_bfloat16 l0 = __float2bfloat16_rn(x0 - __bfloat162float(h0));
    __nv_bfloat16 l1 = __float2bfloat16_rn(x1 - __bfloat162float(h1));
    uint2 r;
    r.x = (uint32_t)__bfloat16_as_ushort(h0) | ((uint32_t)__bfloat16_as_ushort(h1) << 16);
    r.y = (uint32_t)__bfloat16_as_ushort(l0) | ((uint32_t)__bfloat16_as_ushort(l1) << 16);
    return r;
}

__device__ __forceinline__ void gemm_body(
    const float* __restrict__ A, const float* __restrict__ W,
    const float* __restrict__ bias, float* __restrict__ C,
    int M, int N, int K, int bxx, int byy, const float* __restrict__ ss)
{
    __shared__ uint2 As2[BM][SS2];
    __shared__ uint2 Bs2[BN][SS2];

    const int t    = threadIdx.x;
    const int lane = t & 31;
    const int wid  = t >> 5;
    const int wm   = wid & 3;
    const int wn   = wid >> 2;
    const int g    = lane >> 2;
    const int t4   = lane & 3;

    const int block_m = byy * BM;
    const int block_n = bxx * BN;

    const int arow_i = t >> 1;
    const int aseg   = (t & 1) * 16;
    const int brow_i = t >> 2;
    const int bseg   = (t & 3) * 8;
    const int gma = block_m + arow_i;
    const float* aptr = A + (size_t)(gma < M ? gma : (M - 1)) * K + aseg;
    const float* bptr = W + (size_t)(block_n + brow_i) * K + bseg;

    float acc[2][4][4];
#pragma unroll
    for (int i = 0; i < 2; i++)
#pragma unroll
        for (int j = 0; j < 4; j++)
#pragma unroll
            for (int l = 0; l < 4; l++) acc[i][j][l] = 0.f;

    float4 pa[4], pb[2];
#pragma unroll
    for (int u = 0; u < 4; u++) pa[u] = *(const float4*)(aptr + u * 4);
#pragma unroll
    for (int u = 0; u < 2; u++) pb[u] = *(const float4*)(bptr + u * 4);

    const int NC = K / BK;
    for (int c = 0; c < NC; c++) {
#pragma unroll
        for (int u = 0; u < 4; u++) {
            uint2 p0 = split2(pa[u].x, pa[u].y);
            uint2 p1 = split2(pa[u].z, pa[u].w);
            asm volatile("st.shared.v4.b32 [%0], {%1,%2,%3,%4};" ::
                "l"(__cvta_generic_to_shared(&As2[arow_i][aseg / 2 + u * 2])),
                "r"(p0.x), "r"(p0.y), "r"(p1.x), "r"(p1.y) : "memory");
        }
#pragma unroll
        for (int u = 0; u < 2; u++) {
            uint2 p0 = split2(pb[u].x, pb[u].y);
            uint2 p1 = split2(pb[u].z, pb[u].w);
            asm volatile("st.shared.v4.b32 [%0], {%1,%2,%3,%4};" ::
                "l"(__cvta_generic_to_shared(&Bs2[brow_i][bseg / 2 + u * 2])),
                "r"(p0.x), "r"(p0.y), "r"(p1.x), "r"(p1.y) : "memory");
        }
        __syncthreads();

        if (c + 1 < NC) {
            const int k1o = (c + 1) * BK;
#pragma unroll
            for (int u = 0; u < 4; u++) pa[u] = *(const float4*)(aptr + k1o + u * 4);
#pragma unroll
            for (int u = 0; u < 2; u++) pb[u] = *(const float4*)(bptr + k1o + u * 4);
        }

#pragma unroll
        for (int kk = 0; kk < 2; kk++) {
            const int kc0 = kk * 8 + t4;
            const int kc1 = kc0 + 4;
            uint32_t ahi[2][4], alo[2][4];
#pragma unroll
            for (int mt = 0; mt < 2; mt++) {
                const int r0 = wm * 32 + mt * 16 + g;
                uint2 v0 = As2[r0][kc0];
                uint2 v1 = As2[r0 + 8][kc0];
                uint2 v2 = As2[r0][kc1];
                uint2 v3 = As2[r0 + 8][kc1];
                ahi[mt][0] = v0.x; alo[mt][0] = v0.y;
                ahi[mt][1] = v1.x; alo[mt][1] = v1.y;
                ahi[mt][2] = v2.x; alo[mt][2] = v2.y;
                ahi[mt][3] = v3.x; alo[mt][3] = v3.y;
            }
            uint32_t bhi[4][2], blo[4][2];
#pragma unroll
            for (int nt = 0; nt < 4; nt++) {
                const int n0 = wn * 32 + nt * 8 + g;
                uint2 u0 = Bs2[n0][kc0];
                uint2 u1 = Bs2[n0][kc1];
                bhi[nt][0] = u0.x; blo[nt][0] = u0.y;
                bhi[nt][1] = u1.x; blo[nt][1] = u1.y;
            }
#pragma unroll
            for (int mt = 0; mt < 2; mt++)
#pragma unroll
                for (int nt = 0; nt < 4; nt++)
                    mma_bf16(acc[mt][nt], ahi[mt][0], ahi[mt][1], ahi[mt][2], ahi[mt][3],
                             bhi[nt][0], bhi[nt][1]);
#pragma unroll
            for (int mt = 0; mt < 2; mt++)
#pragma unroll
                for (int nt = 0; nt < 4; nt++)
                    mma_bf16(acc[mt][nt], ahi[mt][0], ahi[mt][1], ahi[mt][2], ahi[mt][3],
                             blo[nt][0], blo[nt][1]);
#pragma unroll
            for (int mt = 0; mt < 2; mt++)
#pragma unroll
                for (int nt = 0; nt < 4; nt++)
                    mma_bf16(acc[mt][nt], alo[mt][0], alo[mt][1], alo[mt][2], alo[mt][3],
                             bhi[nt][0], bhi[nt][1]);
        }
        __syncthreads();
    }

#pragma unroll
    for (int mt = 0; mt < 2; mt++) {
#pragma unroll
        for (int nt = 0; nt < 4; nt++) {
            const int m0 = block_m + wm * 32 + mt * 16 + g;
            const int n0 = block_n + wn * 32 + nt * 8 + t4 * 2;
            const float bv0 = bias[n0], bv1 = bias[n0 + 1];
#pragma unroll
            for (int h = 0; h < 2; h++) {
                const int m = m0 + h * 8;
                if (m < M) {
                    float o0 = acc[mt][nt][h * 2]     + bv0;
                    float o1 = acc[mt][nt][h * 2 + 1] + bv1;
                    if (ss) {
                        const float alive = (ss[m] != 0.f) ? 1.f : 0.f;
                        o0 = fmaxf(o0, 0.f) * alive;
                        o1 = fmaxf(o1, 0.f) * alive;
                    }
                    *(float2*)&C[(size_t)m * N + n0] = make_float2(o0, o1);
                }
            }
        }
    }
}

__global__ __launch_bounds__(256, 2) void gemm_bf16_kernel(
    const float* __restrict__ A, const float* __restrict__ W,
    const float* __restrict__ bias, float* __restrict__ C,
    int M, int N, int K, const float* __restrict__ ss)
{
    gemm_body(A, W, bias, C, M, N, K, blockIdx.x, blockIdx.y, ss);
}

__global__ __launch_bounds__(256, 2) void gemm_dual_kernel(
    const float* __restrict__ A0, const float* __restrict__ W0,
    const float* __restrict__ b0, float* __restrict__ C0, int M0, int N0,
    const float* __restrict__ A1, const float* __restrict__ W1,
    const float* __restrict__ b1, float* __restrict__ C1, int M1, int N1,
    int K, int nb0)
{
    int b = blockIdx.x;
    if (b < nb0) {
        const int gx = N0 / BN;
        gemm_body(A0, W0, b0, C0, M0, N0, K, b % gx, b / gx, nullptr);
    } else {
        b -= nb0;
        const int gx = N1 / BN;
        gemm_body(A1, W1, b1, C1, M1, N1, K, b % gx, b / gx, nullptr);
    }
}

// ---------------------------------------------------------------------------
// Upfront CSR build for BOTH passes
// ---------------------------------------------------------------------------
__global__ void init_dual_kernel(int* cnt_e, int* cnt_n)
{
    int i = blockIdx.x * blockDim.x + threadIdx.x;
    if (i < N_EDGES) cnt_e[i] = 0;
    if (i < N_NODES) cnt_n[i] = 0;
}

__global__ void hist_dual_kernel(const int* __restrict__ eidx, const int* __restrict__ nidx,
                                 int* __restrict__ cnt_e, int* __restrict__ cnt_n, int nnz)
{
    int i = blockIdx.x * blockDim.x + threadIdx.x;
    if (i < nnz) {
        atomicAdd(&cnt_e[eidx[i]], 1);
        atomicAdd(&cnt_n[nidx[i]], 1);
    }
}

__device__ __forceinline__ void scan_block_body(
    const int* counts, int* offsets, int* partials, int n, int blk)
{
    __shared__ int sh[1024];
    const int t = threadIdx.x;
    const int i = blk * 1024 + t;
    const int x = (i < n) ? counts[i] : 0;
    sh[t] = x;
    __syncthreads();
    for (int off = 1; off < 1024; off <<= 1) {
        int v = (t >= off) ? sh[t - off] : 0;
        __syncthreads();
        sh[t] += v;
        __syncthreads();
    }
    if (i < n) offsets[i] = sh[t] - x;
    if (t == 1023) partials[blk] = sh[1023];
}

#define NB_E ((N_EDGES + 1023) / 1024)   // 10
#define NB_N ((N_NODES + 1023) / 1024)   // 49

__global__ __launch_bounds__(1024) void scan_dual_block_kernel(
    const int* cnt_e, int* off_e, const int* cnt_n, int* off_n, int* partials)
{
    const int b = blockIdx.x;
    if (b < NB_E) scan_block_body(cnt_e, off_e, partials, N_EDGES, b);
    else          scan_block_body(cnt_n, off_n, partials + 16, N_NODES, b - NB_E);
}

__global__ void scan_serial_kernel(int* partials, int* off_e, int* off_n)
{
    if (threadIdx.x == 0) {
        int run = 0;
        for (int i = 0; i < NB_E; i++) { int t = partials[i]; partials[i] = run; run += t; }
        off_e[N_EDGES] = NNZ;
    } else if (threadIdx.x == 1) {
        int run = 0;
        for (int i = 0; i < NB_N; i++) { int t = partials[16 + i]; partials[16 + i] = run; run += t; }
        off_n[N_NODES] = NNZ;
    }
}

__global__ void scan_add_dual_kernel(int* off_e, int* cur_e, int* off_n, int* cur_n,
                                     const int* partials)
{
    int i = blockIdx.x * blockDim.x + threadIdx.x;
    if (i < N_EDGES) {
        int v = off_e[i] + partials[i >> 10];
        off_e[i] = v;
        cur_e[i] = v;
    }
    if (i < N_NODES) {
        int v = off_n[i] + partials[16 + (i >> 10)];
        off_n[i] = v;
        cur_n[i] = v;
    }
}

// one pass over the incidence list builds BOTH CSR row arrays
__global__ void build_perm_dual_kernel(
    const int* __restrict__ nidx, const int* __restrict__ eidx,
    int* __restrict__ cur_e, int* __restrict__ cur_n,
    int* __restrict__ rows_e, int* __restrict__ rows_n, int nnz)
{
    int i = blockIdx.x * blockDim.x + threadIdx.x;
    if (i < nnz) {
        const int n = nidx[i];
        const int e = eidx[i];
        rows_e[atomicAdd(&cur_e[e], 1)] = n;   // pass 1: segment = edge, row = node
        rows_n[atomicAdd(&cur_n[n], 1)] = e;   // pass 2: segment = node, row = edge
    }
}

// ---------------------------------------------------------------------------
// Fused attention pass: score + exp + weighted aggregate, one block/segment.
// No max pass (scores O(1); softmax shift-invariant). q loaded once per block.
// ---------------------------------------------------------------------------
template <bool RELU>
__global__ __launch_bounds__(256) void fused_attn_kernel(
    const float* __restrict__ kmat, int kstride,
    const float* __restrict__ vmat, int vstride, int voff,
    const float* __restrict__ qmat, int qstride,
    const int* __restrict__ rows, const int* __restrict__ offsets,
    float* __restrict__ out, float* __restrict__ ssout, int nseg)
{
    __shared__ int   sh_r[128];
    __shared__ float sh_s[128];
    const int s = blockIdx.x;
    if (s >= nseg) return;
    const int t = threadIdx.x;
    const int lane = t & 31;
    const int wid  = t >> 5;
    const int beg = offsets[s];
    const int end = offsets[s + 1];

    const float4 qf = *(const float4*)&qmat[(size_t)s * qstride + lane * 4];

    float acc = 0.f, wsum = 0.f;
    for (int cb = beg; cb < end; cb += 128) {
        const int cnt = min(128, end - cb);
        if (t < cnt) sh_r[t] = rows[cb + t];
        __syncthreads();

        // scores: warp w handles entries w, w+8, ...
        for (int j = wid; j < cnt; j += 8) {
            const float4 kf = *(const float4*)&kmat[(size_t)sh_r[j] * kstride + lane * 4];
            float d = kf.x * qf.x + kf.y * qf.y + kf.z * qf.z + kf.w * qf.w;
#pragma unroll
            for (int o = 16; o > 0; o >>= 1) d += __shfl_xor_sync(0xffffffffu, d, o);
            if (lane == 0) {
                const float sc = (d >= 0.f ? d : NEG_SLOPE * d) * SCORE_SCALE;
                sh_s[j] = __expf(sc);
            }
        }
        __syncthreads();

        // weighted aggregate (4 independent chains) + wsum
        float p0 = 0.f, p1 = 0.f, p2 = 0.f, p3 = 0.f;
        int j = 0;
        for (; j + 4 <= cnt; j += 4) {
            const float w0 = sh_s[j], w1 = sh_s[j + 1], w2 = sh_s[j + 2], w3 = sh_s[j + 3];
            wsum += (w0 + w1) + (w2 + w3);
            p0 += w0 * vmat[(size_t)sh_r[j]     * vstride + voff + t];
            p1 += w1 * vmat[(size_t)sh_r[j + 1] * vstride + voff + t];
            p2 += w2 * vmat[(size_t)sh_r[j + 2] * vstride + voff + t];
            p3 += w3 * vmat[(size_t)sh_r[j + 3] * vstride + voff + t];
        }
        for (; j < cnt; j++) {
            const float w = sh_s[j];
            wsum += w;
            p0 += w * vmat[(size_t)sh_r[j] * vstride + voff + t];
        }
        acc += (p0 + p1) + (p2 + p3);
        __syncthreads();
    }

    float r = acc / fmaxf(wsum, 1e-20f);
    if (RELU) r = fmaxf(r, 0.f);
    out[(size_t)s * 256 + t] = r;
    if (ssout != nullptr && t == 0) ssout[s] = wsum;
}

// ---------------------------------------------------------------------------
// Launch
// ---------------------------------------------------------------------------
extern "C" void kernel_launch(void* const* d_in, const int* in_sizes, int n_in,
                              void* d_out, int out_size)
{
    const float* vfeat    = (const float*)d_in[0];
    const float* efeat    = (const float*)d_in[1];
    const int*   node_idx = (const int*)d_in[2];
    const int*   edge_idx = (const int*)d_in[3];
    const float* W_vtx = (const float*)d_in[4];  const float* b_vtx = (const float*)d_in[5];
    const float* W_qe  = (const float*)d_in[6];  const float* b_qe  = (const float*)d_in[7];
    const float* W_kv  = (const float*)d_in[8];  const float* b_kv  = (const float*)d_in[9];
    const float* W_vv  = (const float*)d_in[10]; const float* b_vv  = (const float*)d_in[11];
    const float* W_qv  = (const float*)d_in[12]; const float* b_qv  = (const float*)d_in[13];
    const float* W_ke  = (const float*)d_in[14]; const float* b_ke  = (const float*)d_in[15];
    const float* W_ve  = (const float*)d_in[16]; const float* b_ve  = (const float*)d_in[17];

    float* out_v = (float*)d_out;
    float* out_e = out_v + (size_t)N_NODES * VDIM;

    float *fused1, *fused2, *q1, *agg1, *Wcomb, *bcomb, *Wcat2, *bcat2, *ss_e;
    int *cnt_e, *cnt_n, *off_e, *off_n, *cur_e, *cur_n, *rows_e, *rows_n, *partials;
    cudaGetSymbolAddress((void**)&fused1, g_fused1);
    cudaGetSymbolAddress((void**)&fused2, g_fused2);
    cudaGetSymbolAddress((void**)&q1, g_q1);
    cudaGetSymbolAddress((void**)&agg1, g_agg1);
    cudaGetSymbolAddress((void**)&Wcomb, g_Wcomb);
    cudaGetSymbolAddress((void**)&bcomb, g_bcomb);
    cudaGetSymbolAddress((void**)&Wcat2, g_Wcat2);
    cudaGetSymbolAddress((void**)&bcat2, g_bcat2);
    cudaGetSymbolAddress((void**)&cnt_e, g_cnt_e);
    cudaGetSymbolAddress((void**)&cnt_n, g_cnt_n);
    cudaGetSymbolAddress((void**)&off_e, g_off_e);
    cudaGetSymbolAddress((void**)&off_n, g_off_n);
    cudaGetSymbolAddress((void**)&cur_e, g_cur_e);
    cudaGetSymbolAddress((void**)&cur_n, g_cur_n);
    cudaGetSymbolAddress((void**)&ss_e, g_segsum_e);
    cudaGetSymbolAddress((void**)&rows_e, g_rows_e);
    cudaGetSymbolAddress((void**)&rows_n, g_rows_n);
    cudaGetSymbolAddress((void**)&partials, g_partials);

    const int nnzBlocks = (NNZ + 255) / 256;

    // ---- weight pre-combination + concat ----
    combine_w_kernel<<<512 / 8, 256>>>(W_kv, W_qv, W_vv, W_vtx, Wcomb);
    combine_b_kernel<<<2, 256>>>(W_kv, W_qv, W_vv, b_kv, b_qv, b_vv, b_vtx, bcomb);
    cudaMemcpyAsync(Wcat2,             W_ke, (size_t)QDIM * EDIM * 4, cudaMemcpyDeviceToDevice);
    cudaMemcpyAsync(Wcat2 + 128 * 256, W_ve, (size_t)VDIM * EDIM * 4, cudaMemcpyDeviceToDevice);
    cudaMemcpyAsync(bcat2,       b_ke, QDIM * 4, cudaMemcpyDeviceToDevice);
    cudaMemcpyAsync(bcat2 + 128, b_ve, VDIM * 4, cudaMemcpyDeviceToDevice);

    // ---- upfront CSR build for both passes (counts, offsets, row arrays) ----
    init_dual_kernel<<<(N_NODES + 255) / 256, 256>>>(cnt_e, cnt_n);
    hist_dual_kernel<<<nnzBlocks, 256>>>(edge_idx, node_idx, cnt_e, cnt_n, NNZ);
    scan_dual_block_kernel<<<NB_E + NB_N, 1024>>>(cnt_e, off_e, cnt_n, off_n, partials);
    scan_serial_kernel<<<1, 32>>>(partials, off_e, off_n);
    scan_add_dual_kernel<<<(N_NODES + 255) / 256, 256>>>(off_e, cur_e, off_n, cur_n, partials);
    build_perm_dual_kernel<<<nnzBlocks, 256>>>(node_idx, edge_idx, cur_e, cur_n,
                                               rows_e, rows_n, NNZ);

    // ---- projections: fused1 (k1|q2, 256-wide) + q1 in one launch ----
    {
        const int nb0 = (F1W / BN) * ((N_NODES + BM - 1) / BM);   // 4 * 391
        const int nb1 = (QDIM / BN) * ((N_EDGES + BM - 1) / BM);  // 2 * 79
        gemm_dual_kernel<<<nb0 + nb1, 256>>>(
            vfeat, Wcomb, bcomb, fused1, N_NODES, F1W,
            efeat, W_qe,  b_qe,  q1,     N_EDGES, QDIM,
            KIN, nb0);
    }

    // ---- pass 1: nodes -> hyperedges (fused score+aggregate on raw vfeat) ----
    fused_attn_kernel<false><<<N_EDGES, 256>>>(
        fused1, F1W,          // k1 at col 0
        vfeat, KIN, 0,        // aggregate raw vfeat (projection-commute)
        q1, QDIM,
        rows_e, off_e, agg1, ss_e, N_EDGES);

    // post-GEMM: out_e = relu(agg1 @ Wvvc^T + bvvc), zero where segment empty
    gemm_bf16_kernel<<<dim3(256 / BN, (N_EDGES + BM - 1) / BM), 256>>>(
        agg1, Wcomb + 256 * 256, bcomb + 256, out_e, N_EDGES, 256, 256, ss_e);

    // ---- edge-side fused projection (k2|v2) ----
    gemm_bf16_kernel<<<dim3(F2W / BN, (N_EDGES + BM - 1) / BM), 256>>>(
        out_e, Wcat2, bcat2, fused2, N_EDGES, F2W, EDIM, nullptr);

    // ---- pass 2: hyperedges -> nodes (fused; k and v share fused2 rows) ----
    fused_attn_kernel<true><<<N_NODES, 256>>>(
        fused2, F2W,          // k2 at col 0
        fused2, F2W, 128,     // v2 at col 128 of the same row
        fused1 + 128, F1W,    // q2 at col 128 of fused1
        rows_n, off_n, out_v, nullptr, N_NODES);
}

// round 17
// speedup vs baseline: 1.3696x; 1.1409x over previous
#include <cuda_runtime.h>
#include <cuda_bf16.h>
#include <math.h>
#include <stdint.h>

// ---------------------------------------------------------------------------
// Problem constants
// ---------------------------------------------------------------------------
#define N_NODES 50000
#define N_EDGES 10000
#define NNZ     400000
#define QDIM    128
#define VDIM    256
#define EDIM    256
#define KIN     256
#define NEG_SLOPE 0.01f
#define SCORE_SCALE 0.08838834764831845f   // 1/sqrt(128)

#define F1W 256   // k1 | q2   (v1 eliminated via projection-commute trick)
#define F2W 384   // k2 | v2

// ---------------------------------------------------------------------------
// Static scratch
// ---------------------------------------------------------------------------
__device__ float g_fused1[N_NODES * F1W];
__device__ float g_fused2[N_EDGES * F2W];
__device__ float g_q1[N_EDGES * QDIM];
__device__ float g_agg1[N_EDGES * 256];
__device__ float g_Wcomb[512 * KIN];     // rows: kvc(0-127) | qvc(128-255) | vvc(256-511)
__device__ float g_bcomb[512];
__device__ float g_Wcat2[F2W * EDIM];
__device__ float g_bcat2[F2W];
__device__ int   g_cnt_e[N_EDGES];
__device__ int   g_cnt_n[N_NODES];
__device__ int   g_off_e[N_EDGES + 1];
__device__ int   g_off_n[N_NODES + 1];
__device__ int   g_cur_e[N_EDGES];
__device__ int   g_cur_n[N_NODES];
__device__ float g_segsum_e[N_EDGES];
__device__ int   g_rows_e[NNZ];          // pass-1 CSR: node rows grouped by edge
__device__ int   g_rows_n[NNZ];          // pass-2 CSR: edge rows grouped by node
__device__ int   g_partials[80];

// ---------------------------------------------------------------------------
// Weight pre-combination: row o of Wcomb = (Wsel row) @ Wvtx
// layout: o in [0,128)=W_kv, [128,256)=W_qv, [256,512)=W_vv
// ---------------------------------------------------------------------------
__device__ __forceinline__ const float* comb_src(
    int o, const float* Wkv, const float* Wqv, const float* Wvv)
{
    return (o < 128) ? Wkv + (size_t)o * 256
         : (o < 256) ? Wqv + (size_t)(o - 128) * 256
                     : Wvv + (size_t)(o - 256) * 256;
}

__global__ __launch_bounds__(256) void combine_w_kernel(
    const float* __restrict__ Wkv, const float* __restrict__ Wqv,
    const float* __restrict__ Wvv, const float* __restrict__ Wvtx,
    float* __restrict__ Wcomb)
{
    __shared__ float a[8][256];
    const int ob = blockIdx.x * 8;
    const int i = threadIdx.x;
#pragma unroll
    for (int r = 0; r < 8; r++)
        a[r][i] = comb_src(ob + r, Wkv, Wqv, Wvv)[i];
    __syncthreads();
    float s[8];
#pragma unroll
    for (int r = 0; r < 8; r++) s[r] = 0.f;
    for (int v = 0; v < 256; v++) {
        const float w = Wvtx[(size_t)v * 256 + i];
#pragma unroll
        for (int r = 0; r < 8; r++) s[r] += a[r][v] * w;
    }
#pragma unroll
    for (int r = 0; r < 8; r++) Wcomb[(size_t)(ob + r) * 256 + i] = s[r];
}

__global__ void combine_b_kernel(
    const float* __restrict__ Wkv, const float* __restrict__ Wqv,
    const float* __restrict__ Wvv,
    const float* __restrict__ bkv, const float* __restrict__ bqv,
    const float* __restrict__ bvv, const float* __restrict__ bvtx,
    float* __restrict__ bcomb)
{
    const int o = blockIdx.x * blockDim.x + threadIdx.x;
    if (o >= 512) return;
    const float* wsrc = comb_src(o, Wkv, Wqv, Wvv);
    float b = (o < 128) ? bkv[o] : (o < 256) ? bqv[o - 128] : bvv[o - 256];
    float s = b;
    for (int v = 0; v < 256; v++) s += wsrc[v] * bvtx[v];
    bcomb[o] = s;
}

// ---------------------------------------------------------------------------
// bf16-split tensor-core GEMM body (proven inner loop).
// epilogue: if ss != nullptr -> relu, and zero row when ss[m]==0 (empty seg).
// ---------------------------------------------------------------------------
#define BM 128
#define BN 64
#define BK 32
#define SS2 20

__device__ __forceinline__ void mma_bf16(float* c,
    uint32_t a0, uint32_t a1, uint32_t a2, uint32_t a3,
    uint32_t b0, uint32_t b1)
{
    asm volatile(
        "mma.sync.aligned.m16n8k16.row.col.f32.bf16.bf16.f32 "
        "{%0,%1,%2,%3}, {%4,%5,%6,%7}, {%8,%9}, {%0,%1,%2,%3};"
        : "+f"(c[0]), "+f"(c[1]), "+f"(c[2]), "+f"(c[3])
        : "r"(a0), "r"(a1), "r"(a2), "r"(a3), "r"(b0), "r"(b1));
}

__device__ __forceinline__ uint2 split2(float x0, float x1)
{
    __nv_bfloat16 h0 = __float2bfloat16_rn(x0);
    __nv_bfloat16 h1 = __float2bfloat16_rn(x1);
    __nv_bfloat16 l0 = __float2bfloat16_rn(x0 - __bfloat162float(h0));
    __nv_bfloat16 l1 = __float2bfloat16_rn(x1 - __bfloat162float(h1));
    uint2 r;
    r.x = (uint32_t)__bfloat16_as_ushort(h0) | ((uint32_t)__bfloat16_as_ushort(h1) << 16);
    r.y = (uint32_t)__bfloat16_as_ushort(l0) | ((uint32_t)__bfloat16_as_ushort(l1) << 16);
    return r;
}

__device__ __forceinline__ void gemm_body(
    const float* __restrict__ A, const float* __restrict__ W,
    const float* __restrict__ bias, float* __restrict__ C,
    int M, int N, int K, int bxx, int byy, const float* __restrict__ ss)
{
    __shared__ uint2 As2[BM][SS2];
    __shared__ uint2 Bs2[BN][SS2];

    const int t    = threadIdx.x;
    const int lane = t & 31;
    const int wid  = t >> 5;
    const int wm   = wid & 3;
    const int wn   = wid >> 2;
    const int g    = lane >> 2;
    const int t4   = lane & 3;

    const int block_m = byy * BM;
    const int block_n = bxx * BN;

    const int arow_i = t >> 1;
    const int aseg   = (t & 1) * 16;
    const int brow_i = t >> 2;
    const int bseg   = (t & 3) * 8;
    const int gma = block_m + arow_i;
    const float* aptr = A + (size_t)(gma < M ? gma : (M - 1)) * K + aseg;
    const float* bptr = W + (size_t)(block_n + brow_i) * K + bseg;

    float acc[2][4][4];
#pragma unroll
    for (int i = 0; i < 2; i++)
#pragma unroll
        for (int j = 0; j < 4; j++)
#pragma unroll
            for (int l = 0; l < 4; l++) acc[i][j][l] = 0.f;

    float4 pa[4], pb[2];
#pragma unroll
    for (int u = 0; u < 4; u++) pa[u] = *(const float4*)(aptr + u * 4);
#pragma unroll
    for (int u = 0; u < 2; u++) pb[u] = *(const float4*)(bptr + u * 4);

    const int NC = K / BK;
    for (int c = 0; c < NC; c++) {
#pragma unroll
        for (int u = 0; u < 4; u++) {
            uint2 p0 = split2(pa[u].x, pa[u].y);
            uint2 p1 = split2(pa[u].z, pa[u].w);
            asm volatile("st.shared.v4.b32 [%0], {%1,%2,%3,%4};" ::
                "l"(__cvta_generic_to_shared(&As2[arow_i][aseg / 2 + u * 2])),
                "r"(p0.x), "r"(p0.y), "r"(p1.x), "r"(p1.y) : "memory");
        }
#pragma unroll
        for (int u = 0; u < 2; u++) {
            uint2 p0 = split2(pb[u].x, pb[u].y);
            uint2 p1 = split2(pb[u].z, pb[u].w);
            asm volatile("st.shared.v4.b32 [%0], {%1,%2,%3,%4};" ::
                "l"(__cvta_generic_to_shared(&Bs2[brow_i][bseg / 2 + u * 2])),
                "r"(p0.x), "r"(p0.y), "r"(p1.x), "r"(p1.y) : "memory");
        }
        __syncthreads();

        if (c + 1 < NC) {
            const int k1o = (c + 1) * BK;
#pragma unroll
            for (int u = 0; u < 4; u++) pa[u] = *(const float4*)(aptr + k1o + u * 4);
#pragma unroll
            for (int u = 0; u < 2; u++) pb[u] = *(const float4*)(bptr + k1o + u * 4);
        }

#pragma unroll
        for (int kk = 0; kk < 2; kk++) {
            const int kc0 = kk * 8 + t4;
            const int kc1 = kc0 + 4;
            uint32_t ahi[2][4], alo[2][4];
#pragma unroll
            for (int mt = 0; mt < 2; mt++) {
                const int r0 = wm * 32 + mt * 16 + g;
                uint2 v0 = As2[r0][kc0];
                uint2 v1 = As2[r0 + 8][kc0];
                uint2 v2 = As2[r0][kc1];
                uint2 v3 = As2[r0 + 8][kc1];
                ahi[mt][0] = v0.x; alo[mt][0] = v0.y;
                ahi[mt][1] = v1.x; alo[mt][1] = v1.y;
                ahi[mt][2] = v2.x; alo[mt][2] = v2.y;
                ahi[mt][3] = v3.x; alo[mt][3] = v3.y;
            }
            uint32_t bhi[4][2], blo[4][2];
#pragma unroll
            for (int nt = 0; nt < 4; nt++) {
                const int n0 = wn * 32 + nt * 8 + g;
                uint2 u0 = Bs2[n0][kc0];
                uint2 u1 = Bs2[n0][kc1];
                bhi[nt][0] = u0.x; blo[nt][0] = u0.y;
                bhi[nt][1] = u1.x; blo[nt][1] = u1.y;
            }
#pragma unroll
            for (int mt = 0; mt < 2; mt++)
#pragma unroll
                for (int nt = 0; nt < 4; nt++)
                    mma_bf16(acc[mt][nt], ahi[mt][0], ahi[mt][1], ahi[mt][2], ahi[mt][3],
                             bhi[nt][0], bhi[nt][1]);
#pragma unroll
            for (int mt = 0; mt < 2; mt++)
#pragma unroll
                for (int nt = 0; nt < 4; nt++)
                    mma_bf16(acc[mt][nt], ahi[mt][0], ahi[mt][1], ahi[mt][2], ahi[mt][3],
                             blo[nt][0], blo[nt][1]);
#pragma unroll
            for (int mt = 0; mt < 2; mt++)
#pragma unroll
                for (int nt = 0; nt < 4; nt++)
                    mma_bf16(acc[mt][nt], alo[mt][0], alo[mt][1], alo[mt][2], alo[mt][3],
                             bhi[nt][0], bhi[nt][1]);
        }
        __syncthreads();
    }

#pragma unroll
    for (int mt = 0; mt < 2; mt++) {
#pragma unroll
        for (int nt = 0; nt < 4; nt++) {
            const int m0 = block_m + wm * 32 + mt * 16 + g;
            const int n0 = block_n + wn * 32 + nt * 8 + t4 * 2;
            const float bv0 = bias[n0], bv1 = bias[n0 + 1];
#pragma unroll
            for (int h = 0; h < 2; h++) {
                const int m = m0 + h * 8;
                if (m < M) {
                    float o0 = acc[mt][nt][h * 2]     + bv0;
                    float o1 = acc[mt][nt][h * 2 + 1] + bv1;
                    if (ss) {
                        const float alive = (ss[m] != 0.f) ? 1.f : 0.f;
                        o0 = fmaxf(o0, 0.f) * alive;
                        o1 = fmaxf(o1, 0.f) * alive;
                    }
                    *(float2*)&C[(size_t)m * N + n0] = make_float2(o0, o1);
                }
            }
        }
    }
}

__global__ __launch_bounds__(256, 2) void gemm_bf16_kernel(
    const float* __restrict__ A, const float* __restrict__ W,
    const float* __restrict__ bias, float* __restrict__ C,
    int M, int N, int K, const float* __restrict__ ss)
{
    gemm_body(A, W, bias, C, M, N, K, blockIdx.x, blockIdx.y, ss);
}

__global__ __launch_bounds__(256, 2) void gemm_dual_kernel(
    const float* __restrict__ A0, const float* __restrict__ W0,
    const float* __restrict__ b0, float* __restrict__ C0, int M0, int N0,
    const float* __restrict__ A1, const float* __restrict__ W1,
    const float* __restrict__ b1, float* __restrict__ C1, int M1, int N1,
    int K, int nb0)
{
    int b = blockIdx.x;
    if (b < nb0) {
        const int gx = N0 / BN;
        gemm_body(A0, W0, b0, C0, M0, N0, K, b % gx, b / gx, nullptr);
    } else {
        b -= nb0;
        const int gx = N1 / BN;
        gemm_body(A1, W1, b1, C1, M1, N1, K, b % gx, b / gx, nullptr);
    }
}

// ---------------------------------------------------------------------------
// Upfront CSR build for BOTH passes
// ---------------------------------------------------------------------------
__global__ void init_dual_kernel(int* cnt_e, int* cnt_n)
{
    int i = blockIdx.x * blockDim.x + threadIdx.x;
    if (i < N_EDGES) cnt_e[i] = 0;
    if (i < N_NODES) cnt_n[i] = 0;
}

__global__ void hist_dual_kernel(const int* __restrict__ eidx, const int* __restrict__ nidx,
                                 int* __restrict__ cnt_e, int* __restrict__ cnt_n, int nnz)
{
    int i = blockIdx.x * blockDim.x + threadIdx.x;
    if (i < nnz) {
        atomicAdd(&cnt_e[eidx[i]], 1);
        atomicAdd(&cnt_n[nidx[i]], 1);
    }
}

__device__ __forceinline__ void scan_block_body(
    const int* counts, int* offsets, int* partials, int n, int blk)
{
    __shared__ int sh[1024];
    const int t = threadIdx.x;
    const int i = blk * 1024 + t;
    const int x = (i < n) ? counts[i] : 0;
    sh[t] = x;
    __syncthreads();
    for (int off = 1; off < 1024; off <<= 1) {
        int v = (t >= off) ? sh[t - off] : 0;
        __syncthreads();
        sh[t] += v;
        __syncthreads();
    }
    if (i < n) offsets[i] = sh[t] - x;
    if (t == 1023) partials[blk] = sh[1023];
}

#define NB_E ((N_EDGES + 1023) / 1024)   // 10
#define NB_N ((N_NODES + 1023) / 1024)   // 49

__global__ __launch_bounds__(1024) void scan_dual_block_kernel(
    const int* cnt_e, int* off_e, const int* cnt_n, int* off_n, int* partials)
{
    const int b = blockIdx.x;
    if (b < NB_E) scan_block_body(cnt_e, off_e, partials, N_EDGES, b);
    else          scan_block_body(cnt_n, off_n, partials + 16, N_NODES, b - NB_E);
}

__global__ void scan_serial_kernel(int* partials, int* off_e, int* off_n)
{
    if (threadIdx.x == 0) {
        int run = 0;
        for (int i = 0; i < NB_E; i++) { int t = partials[i]; partials[i] = run; run += t; }
        off_e[N_EDGES] = NNZ;
    } else if (threadIdx.x == 1) {
        int run = 0;
        for (int i = 0; i < NB_N; i++) { int t = partials[16 + i]; partials[16 + i] = run; run += t; }
        off_n[N_NODES] = NNZ;
    }
}

__global__ void scan_add_dual_kernel(int* off_e, int* cur_e, int* off_n, int* cur_n,
                                     const int* partials)
{
    int i = blockIdx.x * blockDim.x + threadIdx.x;
    if (i < N_EDGES) {
        int v = off_e[i] + partials[i >> 10];
        off_e[i] = v;
        cur_e[i] = v;
    }
    if (i < N_NODES) {
        int v = off_n[i] + partials[16 + (i >> 10)];
        off_n[i] = v;
        cur_n[i] = v;
    }
}

// one pass over the incidence list builds BOTH CSR row arrays
__global__ void build_perm_dual_kernel(
    const int* __restrict__ nidx, const int* __restrict__ eidx,
    int* __restrict__ cur_e, int* __restrict__ cur_n,
    int* __restrict__ rows_e, int* __restrict__ rows_n, int nnz)
{
    int i = blockIdx.x * blockDim.x + threadIdx.x;
    if (i < nnz) {
        const int n = nidx[i];
        const int e = eidx[i];
        rows_e[atomicAdd(&cur_e[e], 1)] = n;   // pass 1: segment = edge, row = node
        rows_n[atomicAdd(&cur_n[n], 1)] = e;   // pass 2: segment = node, row = edge
    }
}

// ---------------------------------------------------------------------------
// Fused attention pass: score + exp + weighted aggregate, one block/segment.
// 128 threads; each thread owns 2 output dims (float2 v loads/stores).
// No max pass (scores O(1); softmax shift-invariant). q loaded once per block.
// ---------------------------------------------------------------------------
template <bool RELU>
__global__ __launch_bounds__(128) void fused_attn_kernel(
    const float* __restrict__ kmat, int kstride,
    const float* __restrict__ vmat, int vstride, int voff,
    const float* __restrict__ qmat, int qstride,
    const int* __restrict__ rows, const int* __restrict__ offsets,
    float* __restrict__ out, float* __restrict__ ssout, int nseg)
{
    __shared__ int   sh_r[128];
    __shared__ float sh_s[128];
    const int s = blockIdx.x;
    if (s >= nseg) return;
    const int t = threadIdx.x;
    const int lane = t & 31;
    const int wid  = t >> 5;        // 0..3
    const int beg = offsets[s];
    const int end = offsets[s + 1];

    const float4 qf = *(const float4*)&qmat[(size_t)s * qstride + lane * 4];

    float2 acc = make_float2(0.f, 0.f);
    float wsum = 0.f;
    for (int cb = beg; cb < end; cb += 128) {
        const int cnt = min(128, end - cb);
        if (t < cnt) sh_r[t] = rows[cb + t];
        __syncthreads();

        // scores: warp w handles entries w, w+4, ...
        for (int j = wid; j < cnt; j += 4) {
            const float4 kf = *(const float4*)&kmat[(size_t)sh_r[j] * kstride + lane * 4];
            float d = kf.x * qf.x + kf.y * qf.y + kf.z * qf.z + kf.w * qf.w;
#pragma unroll
            for (int o = 16; o > 0; o >>= 1) d += __shfl_xor_sync(0xffffffffu, d, o);
            if (lane == 0) {
                const float sc = (d >= 0.f ? d : NEG_SLOPE * d) * SCORE_SCALE;
                sh_s[j] = __expf(sc);
            }
        }
        __syncthreads();

        // weighted aggregate: 2 dims per thread, 4 independent chains
        const int dc = voff + t * 2;
        float2 p0 = make_float2(0.f, 0.f), p1 = make_float2(0.f, 0.f);
        float2 p2 = make_float2(0.f, 0.f), p3 = make_float2(0.f, 0.f);
        int j = 0;
        for (; j + 4 <= cnt; j += 4) {
            const float w0 = sh_s[j], w1 = sh_s[j + 1], w2 = sh_s[j + 2], w3 = sh_s[j + 3];
            wsum += (w0 + w1) + (w2 + w3);
            const float2 v0 = *(const float2*)&vmat[(size_t)sh_r[j]     * vstride + dc];
            const float2 v1 = *(const float2*)&vmat[(size_t)sh_r[j + 1] * vstride + dc];
            const float2 v2 = *(const float2*)&vmat[(size_t)sh_r[j + 2] * vstride + dc];
            const float2 v3 = *(const float2*)&vmat[(size_t)sh_r[j + 3] * vstride + dc];
            p0.x += w0 * v0.x; p0.y += w0 * v0.y;
            p1.x += w1 * v1.x; p1.y += w1 * v1.y;
            p2.x += w2 * v2.x; p2.y += w2 * v2.y;
            p3.x += w3 * v3.x; p3.y += w3 * v3.y;
        }
        for (; j < cnt; j++) {
            const float w = sh_s[j];
            wsum += w;
            const float2 v = *(const float2*)&vmat[(size_t)sh_r[j] * vstride + dc];
            p0.x += w * v.x; p0.y += w * v.y;
        }
        acc.x += (p0.x + p1.x) + (p2.x + p3.x);
        acc.y += (p0.y + p1.y) + (p2.y + p3.y);
        __syncthreads();
    }

    const float inv = 1.f / fmaxf(wsum, 1e-20f);
    float r0 = acc.x * inv, r1 = acc.y * inv;
    if (RELU) { r0 = fmaxf(r0, 0.f); r1 = fmaxf(r1, 0.f); }
    *(float2*)&out[(size_t)s * 256 + t * 2] = make_float2(r0, r1);
    if (ssout != nullptr && t == 0) ssout[s] = wsum;
}

// ---------------------------------------------------------------------------
// Launch
// ---------------------------------------------------------------------------
extern "C" void kernel_launch(void* const* d_in, const int* in_sizes, int n_in,
                              void* d_out, int out_size)
{
    const float* vfeat    = (const float*)d_in[0];
    const float* efeat    = (const float*)d_in[1];
    const int*   node_idx = (const int*)d_in[2];
    const int*   edge_idx = (const int*)d_in[3];
    const float* W_vtx = (const float*)d_in[4];  const float* b_vtx = (const float*)d_in[5];
    const float* W_qe  = (const float*)d_in[6];  const float* b_qe  = (const float*)d_in[7];
    const float* W_kv  = (const float*)d_in[8];  const float* b_kv  = (const float*)d_in[9];
    const float* W_vv  = (const float*)d_in[10]; const float* b_vv  = (const float*)d_in[11];
    const float* W_qv  = (const float*)d_in[12]; const float* b_qv  = (const float*)d_in[13];
    const float* W_ke  = (const float*)d_in[14]; const float* b_ke  = (const float*)d_in[15];
    const float* W_ve  = (const float*)d_in[16]; const float* b_ve  = (const float*)d_in[17];

    float* out_v = (float*)d_out;
    float* out_e = out_v + (size_t)N_NODES * VDIM;

    float *fused1, *fused2, *q1, *agg1, *Wcomb, *bcomb, *Wcat2, *bcat2, *ss_e;
    int *cnt_e, *cnt_n, *off_e, *off_n, *cur_e, *cur_n, *rows_e, *rows_n, *partials;
    cudaGetSymbolAddress((void**)&fused1, g_fused1);
    cudaGetSymbolAddress((void**)&fused2, g_fused2);
    cudaGetSymbolAddress((void**)&q1, g_q1);
    cudaGetSymbolAddress((void**)&agg1, g_agg1);
    cudaGetSymbolAddress((void**)&Wcomb, g_Wcomb);
    cudaGetSymbolAddress((void**)&bcomb, g_bcomb);
    cudaGetSymbolAddress((void**)&Wcat2, g_Wcat2);
    cudaGetSymbolAddress((void**)&bcat2, g_bcat2);
    cudaGetSymbolAddress((void**)&cnt_e, g_cnt_e);
    cudaGetSymbolAddress((void**)&cnt_n, g_cnt_n);
    cudaGetSymbolAddress((void**)&off_e, g_off_e);
    cudaGetSymbolAddress((void**)&off_n, g_off_n);
    cudaGetSymbolAddress((void**)&cur_e, g_cur_e);
    cudaGetSymbolAddress((void**)&cur_n, g_cur_n);
    cudaGetSymbolAddress((void**)&ss_e, g_segsum_e);
    cudaGetSymbolAddress((void**)&rows_e, g_rows_e);
    cudaGetSymbolAddress((void**)&rows_n, g_rows_n);
    cudaGetSymbolAddress((void**)&partials, g_partials);

    const int nnzBlocks = (NNZ + 255) / 256;

    // ---- weight pre-combination + concat ----
    combine_w_kernel<<<512 / 8, 256>>>(W_kv, W_qv, W_vv, W_vtx, Wcomb);
    combine_b_kernel<<<2, 256>>>(W_kv, W_qv, W_vv, b_kv, b_qv, b_vv, b_vtx, bcomb);
    cudaMemcpyAsync(Wcat2,             W_ke, (size_t)QDIM * EDIM * 4, cudaMemcpyDeviceToDevice);
    cudaMemcpyAsync(Wcat2 + 128 * 256, W_ve, (size_t)VDIM * EDIM * 4, cudaMemcpyDeviceToDevice);
    cudaMemcpyAsync(bcat2,       b_ke, QDIM * 4, cudaMemcpyDeviceToDevice);
    cudaMemcpyAsync(bcat2 + 128, b_ve, VDIM * 4, cudaMemcpyDeviceToDevice);

    // ---- upfront CSR build for both passes (counts, offsets, row arrays) ----
    init_dual_kernel<<<(N_NODES + 255) / 256, 256>>>(cnt_e, cnt_n);
    hist_dual_kernel<<<nnzBlocks, 256>>>(edge_idx, node_idx, cnt_e, cnt_n, NNZ);
    scan_dual_block_kernel<<<NB_E + NB_N, 1024>>>(cnt_e, off_e, cnt_n, off_n, partials);
    scan_serial_kernel<<<1, 32>>>(partials, off_e, off_n);
    scan_add_dual_kernel<<<(N_NODES + 255) / 256, 256>>>(off_e, cur_e, off_n, cur_n, partials);
    build_perm_dual_kernel<<<nnzBlocks, 256>>>(node_idx, edge_idx, cur_e, cur_n,
                                               rows_e, rows_n, NNZ);

    // ---- projections: fused1 (k1|q2, 256-wide) + q1 in one launch ----
    {
        const int nb0 = (F1W / BN) * ((N_NODES + BM - 1) / BM);   // 4 * 391
        const int nb1 = (QDIM / BN) * ((N_EDGES + BM - 1) / BM);  // 2 * 79
        gemm_dual_kernel<<<nb0 + nb1, 256>>>(
            vfeat, Wcomb, bcomb, fused1, N_NODES, F1W,
            efeat, W_qe,  b_qe,  q1,     N_EDGES, QDIM,
            KIN, nb0);
    }

    // ---- pass 1: nodes -> hyperedges (fused score+aggregate on raw vfeat) ----
    fused_attn_kernel<false><<<N_EDGES, 128>>>(
        fused1, F1W,          // k1 at col 0
        vfeat, KIN, 0,        // aggregate raw vfeat (projection-commute)
        q1, QDIM,
        rows_e, off_e, agg1, ss_e, N_EDGES);

    // post-GEMM: out_e = relu(agg1 @ Wvvc^T + bvvc), zero where segment empty
    gemm_bf16_kernel<<<dim3(256 / BN, (N_EDGES + BM - 1) / BM), 256>>>(
        agg1, Wcomb + 256 * 256, bcomb + 256, out_e, N_EDGES, 256, 256, ss_e);

    // ---- edge-side fused projection (k2|v2) ----
    gemm_bf16_kernel<<<dim3(F2W / BN, (N_EDGES + BM - 1) / BM), 256>>>(
        out_e, Wcat2, bcat2, fused2, N_EDGES, F2W, EDIM, nullptr);

    // ---- pass 2: hyperedges -> nodes (fused; k and v share fused2 rows) ----
    fused_attn_kernel<true><<<N_NODES, 128>>>(
        fused2, F2W,          // k2 at col 0
        fused2, F2W, 128,     // v2 at col 128 of the same row
        fused1 + 128, F1W,    // q2 at col 128 of fused1
        rows_n, off_n, out_v, nullptr, N_NODES);
}